// round 5
// baseline (speedup 1.0000x reference)
#include <cuda_runtime.h>
#include <math.h>
#include <stdint.h>

// ---------------------------------------------------------------------------
// Problem constants
// ---------------------------------------------------------------------------
namespace cfg {
constexpr int B = 2, S = 1024, H = 1024;
constexpr int NH = 8, NKV = 2, D = 128, ROT = 64;
constexpr int E = 64, TK = 8, NG = 8, TG = 4;
constexpr int FI = 512, FSH = 512, CAP = 512;
constexpr int T = B * S;                  // 2048 tokens
constexpr int QKVW = (NH + 2 * NKV) * D;  // 1536
constexpr float EPS = 1e-5f;
constexpr float SCALE = 0.08838834764831843f;  // 128^-0.5
constexpr float THETA = 10000.0f;
}  // namespace cfg

using namespace cfg;

// ---------------------------------------------------------------------------
// Static device scratch (no allocations allowed)
// ---------------------------------------------------------------------------
constexpr size_t N_H      = (size_t)T * H;
constexpr size_t N_QKV    = (size_t)T * QKVW;
constexpr size_t N_Q      = (size_t)T * NH * D;
constexpr size_t N_K      = (size_t)T * NKV * D;
constexpr size_t N_SC     = (size_t)B * NH * S * S;
constexpr size_t N_AOUT   = (size_t)T * NH * D;
constexpr size_t N_H2     = (size_t)T * H;
constexpr size_t N_XT     = (size_t)T * H;
constexpr size_t N_LOG    = (size_t)T * E;
constexpr size_t N_FW     = (size_t)T * TK;
constexpr size_t N_SGU    = (size_t)T * 2 * FSH;
constexpr size_t N_SHACT  = (size_t)T * FSH;
constexpr size_t N_SHARED = (size_t)T * H;
constexpr size_t N_GU     = (size_t)E * CAP * 2 * FI;
constexpr size_t N_ACT    = (size_t)E * CAP * FI;
constexpr size_t N_EO     = (size_t)E * CAP * H;

constexpr size_t OFF_H      = 0;
constexpr size_t OFF_QKV    = OFF_H + N_H;
constexpr size_t OFF_Q      = OFF_QKV + N_QKV;
constexpr size_t OFF_K      = OFF_Q + N_Q;
constexpr size_t OFF_SC     = OFF_K + N_K;
constexpr size_t OFF_AOUT   = OFF_SC + N_SC;
constexpr size_t OFF_H2     = OFF_AOUT + N_AOUT;
constexpr size_t OFF_XT     = OFF_H2 + N_H2;
constexpr size_t OFF_LOG    = OFF_XT + N_XT;
constexpr size_t OFF_FW     = OFF_LOG + N_LOG;
constexpr size_t OFF_SGU    = OFF_FW + N_FW;
constexpr size_t OFF_SHACT  = OFF_SGU + N_SGU;
constexpr size_t OFF_SHARED = OFF_SHACT + N_SHACT;
constexpr size_t OFF_GU     = OFF_SHARED + N_SHARED;
constexpr size_t OFF_ACT    = OFF_GU + N_GU;
constexpr size_t OFF_EO     = OFF_ACT + N_ACT;
constexpr size_t SCRATCH_F  = OFF_EO + N_EO;

__device__ float g_scratch[SCRATCH_F];

__device__ int g_topi[T * TK];
__device__ int g_slotpos[T * TK];
__device__ int g_cnt[E];
__device__ int g_tok[E * CAP];

// ---------------------------------------------------------------------------
// mma / cp.async helpers
// ---------------------------------------------------------------------------
__device__ __forceinline__ void mma_tf32(float c[4], const uint32_t a[4],
                                         const uint32_t b[2]) {
  asm volatile(
      "mma.sync.aligned.m16n8k8.row.col.f32.tf32.tf32.f32 "
      "{%0,%1,%2,%3}, {%4,%5,%6,%7}, {%8,%9}, {%0,%1,%2,%3};\n"
      : "+f"(c[0]), "+f"(c[1]), "+f"(c[2]), "+f"(c[3])
      : "r"(a[0]), "r"(a[1]), "r"(a[2]), "r"(a[3]), "r"(b[0]), "r"(b[1]));
}

__device__ __forceinline__ void ldsm4(uint32_t r[4], uint32_t saddr) {
  asm volatile(
      "ldmatrix.sync.aligned.m8n8.x4.shared.b16 {%0,%1,%2,%3}, [%4];"
      : "=r"(r[0]), "=r"(r[1]), "=r"(r[2]), "=r"(r[3])
      : "r"(saddr));
}

__device__ __forceinline__ void cp_async16(uint32_t dst, const void* src,
                                           bool pred) {
  int sz = pred ? 16 : 0;
  asm volatile("cp.async.cg.shared.global [%0], [%1], 16, %2;\n" ::"r"(dst),
               "l"(src), "r"(sz));
}
__device__ __forceinline__ void cp_commit() {
  asm volatile("cp.async.commit_group;\n");
}
template <int N>
__device__ __forceinline__ void cp_wait() {
  asm volatile("cp.async.wait_group %0;\n" ::"n"(N));
}

// ---------------------------------------------------------------------------
// RMSNorm over rows of length `dim`
// ---------------------------------------------------------------------------
__global__ void rmsnorm_kernel(const float* __restrict__ in,
                               const float* __restrict__ w,
                               float* __restrict__ out, int dim) {
  int t = blockIdx.x;
  const float* r = in + (size_t)t * dim;
  float s = 0.f;
  for (int i = threadIdx.x; i < dim; i += 256) {
    float v = r[i];
    s += v * v;
  }
  for (int o = 16; o; o >>= 1) s += __shfl_xor_sync(~0u, s, o);
  __shared__ float red[8];
  if ((threadIdx.x & 31) == 0) red[threadIdx.x >> 5] = s;
  __syncthreads();
  if (threadIdx.x == 0) {
    float tt = 0.f;
    for (int i = 0; i < 8; i++) tt += red[i];
    red[0] = tt;
  }
  __syncthreads();
  float inv = rsqrtf(red[0] / (float)dim + EPS);
  for (int i = threadIdx.x; i < dim; i += 256)
    out[(size_t)t * dim + i] = r[i] * inv * w[i];
}

// ---------------------------------------------------------------------------
// Per-head Q/K RMSNorm + RoPE. grid (T, NH+NKV), block D=128
// ---------------------------------------------------------------------------
__global__ void qknorm_rope_kernel(const float* __restrict__ qkv,
                                   const int* __restrict__ positions,
                                   const float* __restrict__ qn,
                                   const float* __restrict__ kn,
                                   float* __restrict__ qout,
                                   float* __restrict__ kout) {
  int t = blockIdx.x, hh = blockIdx.y, d = threadIdx.x;
  const float* src;
  const float* w;
  float* dst;
  if (hh < NH) {
    src = qkv + (size_t)t * QKVW + hh * D;
    w = qn;
    dst = qout + ((size_t)t * NH + hh) * D;
  } else {
    int kv = hh - NH;
    src = qkv + (size_t)t * QKVW + NH * D + kv * D;
    w = kn;
    dst = kout + ((size_t)t * NKV + kv) * D;
  }
  float v = src[d];
  float s = v * v;
  for (int o = 16; o; o >>= 1) s += __shfl_xor_sync(~0u, s, o);
  __shared__ float red[4];
  if ((d & 31) == 0) red[d >> 5] = s;
  __syncthreads();
  float tot = red[0] + red[1] + red[2] + red[3];
  float nv = v * rsqrtf(tot / (float)D + EPS) * w[d];
  __shared__ float sh[128];
  sh[d] = nv;
  __syncthreads();
  int sidx = t & (S - 1);
  float pos = (float)positions[sidx];
  float res;
  if (d < ROT / 2) {
    float ang = pos * powf(THETA, -(float)d / (float)(ROT / 2));
    res = sh[d] * cosf(ang) - sh[d + ROT / 2] * sinf(ang);
  } else if (d < ROT) {
    int i2 = d - ROT / 2;
    float ang = pos * powf(THETA, -(float)i2 / (float)(ROT / 2));
    res = sh[d] * cosf(ang) + sh[d - ROT / 2] * sinf(ang);
  } else {
    res = nv;
  }
  dst[d] = res;
}

// ---------------------------------------------------------------------------
// GEMM modes
// ---------------------------------------------------------------------------
enum GemmMode {
  M_QKV = 0,   // C = A @ B^T + bias
  M_SCORES,    // per (b,h): C = scale * Q @ K^T, causal (masked part unwritten)
  M_AV,        // per (b,h): C = attn @ V  (V strided inside qkv buffer)
  M_WO,        // C = resid + A @ B^T
  M_GATE,      // C = A @ B^T
  M_SGU,       // C = A @ B   (NN)
  M_SDN,       // C = A @ B   (NN)
  M_MOEGU,     // per expert: gathered-A @ B (NN), rows < cnt[e]
  M_MOEDN      // per expert: A @ B (NN), rows < cnt[e]
};

struct GemmP {
  int mode;
  const float* A;
  const float* Bm;
  float* C;
  const float* bias;
  const float* resid;
  const int* gidx;
  const int* cnt;
  int M, N, K, lda, ldb, ldc;
  int transB;
};

// ---------------------------------------------------------------------------
// Tensor-core tf32 GEMM: 128x128x16 block tile, 256 threads (8 warps 2x4),
// warp tile 64x32, 4-stage cp.async ring in dynamic smem, 2 CTAs/SM,
// single __syncthreads per K-iter.
// A smem [m][APAD], ldmatrix.x4.  B smem: transB -> [n][APAD] (scalar LDS),
// NN -> [k][BPAD] (scalar LDS). Raw fp32 bits into tf32 mma (HW truncation).
// ---------------------------------------------------------------------------
constexpr int APAD = 20;   // words; row stride for [m][k] and [n][k] tiles
constexpr int BPAD = 136;  // words; row stride for [k][n] tiles
constexpr int STAGES = 4;
constexpr int STW = 128 * APAD;  // words per operand per stage (2560)
constexpr int GEMM_DSMEM = STAGES * 2 * STW * 4;  // 81920 bytes

extern __shared__ uint32_t dynsmem[];

__global__ __launch_bounds__(256, 2) void gemm_tc(GemmP p) {
  int z = blockIdx.z;
  const float* Ab = p.A;
  const float* Bb = p.Bm;
  float* Cb = p.C;
  const int* gidx = nullptr;
  int Meff = p.M;

  if (p.mode == M_SCORES) {
    int b = z >> 3, h = z & 7;
    Ab = p.A + ((size_t)(b * S) * NH + h) * D;
    Bb = p.Bm + ((size_t)(b * S) * NKV + (h >> 2)) * D;
    Cb = p.C + (size_t)z * S * S;
  } else if (p.mode == M_AV) {
    int b = z >> 3, h = z & 7;
    Ab = p.A + (size_t)z * S * S;
    Bb = p.Bm + (size_t)(b * S) * QKVW + (size_t)(NH + NKV) * D + (h >> 2) * D;
    Cb = p.C + (size_t)(b * S) * (NH * D) + h * D;
  } else if (p.mode == M_MOEGU) {
    Meff = min(p.cnt[z], CAP);
    gidx = p.gidx + z * CAP;
    Bb = p.Bm + (size_t)z * H * (2 * FI);
    Cb = p.C + (size_t)z * CAP * (2 * FI);
  } else if (p.mode == M_MOEDN) {
    Meff = min(p.cnt[z], CAP);
    Ab = p.A + (size_t)z * CAP * FI;
    Bb = p.Bm + (size_t)z * FI * H;
    Cb = p.C + (size_t)z * CAP * H;
  }

  int m0 = blockIdx.y * 128, n0 = blockIdx.x * 128;
  if (m0 >= Meff) return;
  if (p.mode == M_SCORES && n0 > m0 + 127) return;

  int kend = p.K;
  if (p.mode == M_AV) kend = min(p.K, m0 + 128);
  int nk = kend >> 4;

  uint32_t* Asm = dynsmem;                  // STAGES * STW
  uint32_t* Bsm = dynsmem + STAGES * STW;   // STAGES * STW

  int tid = threadIdx.x;
  int lane = tid & 31, wid = tid >> 5;
  int warp_m = wid & 1, warp_n = wid >> 1;  // 2 x 4
  int gid = lane >> 2, tig = lane & 3;

  uint32_t as_base = (uint32_t)__cvta_generic_to_shared(Asm);
  uint32_t bs_base = (uint32_t)__cvta_generic_to_shared(Bsm);
  int lm_row = (lane & 15);
  int lm_col = (lane >> 4) << 2;

  float acc[4][4][4];
#pragma unroll
  for (int a = 0; a < 4; a++)
#pragma unroll
    for (int b = 0; b < 4; b++)
#pragma unroll
      for (int c = 0; c < 4; c++) acc[a][b][c] = 0.f;

  // per-thread copy indices
  int a_row0 = tid >> 2, a_kq = (tid & 3) * 4;
  const float* a_src0;
  const float* a_src1;
  {
    int gm0 = m0 + a_row0, gm1 = m0 + a_row0 + 64;
    a_src0 = (gm0 < Meff)
                 ? (gidx ? Ab + (size_t)gidx[gm0] * p.lda
                         : Ab + (size_t)gm0 * p.lda)
                 : Ab;
    a_src1 = (gm1 < Meff)
                 ? (gidx ? Ab + (size_t)gidx[gm1] * p.lda
                         : Ab + (size_t)gm1 * p.lda)
                 : Ab;
  }
  bool a_v0 = (m0 + a_row0) < Meff;
  bool a_v1 = (m0 + a_row0 + 64) < Meff;

  // issue k-iter `it` into stage `st`; always commits (possibly empty group)
  auto issue = [&](int it, int st) {
    if (it < nk) {
      int k0 = it << 4;
      cp_async16(as_base + (uint32_t)(st * STW + a_row0 * APAD + a_kq) * 4u,
                 a_src0 + k0 + a_kq, a_v0);
      cp_async16(
          as_base + (uint32_t)(st * STW + (a_row0 + 64) * APAD + a_kq) * 4u,
          a_src1 + k0 + a_kq, a_v1);
      if (p.transB) {
        int n = tid >> 2, kq = (tid & 3) * 4;
        cp_async16(bs_base + (uint32_t)(st * STW + n * APAD + kq) * 4u,
                   Bb + (size_t)(n0 + n) * p.ldb + k0 + kq, true);
        cp_async16(bs_base + (uint32_t)(st * STW + (n + 64) * APAD + kq) * 4u,
                   Bb + (size_t)(n0 + n + 64) * p.ldb + k0 + kq, true);
      } else {
        int kk = tid >> 5, nq = (tid & 31) * 4;
        cp_async16(bs_base + (uint32_t)(st * STW + kk * BPAD + nq) * 4u,
                   Bb + (size_t)(k0 + kk) * p.ldb + n0 + nq, true);
        cp_async16(bs_base + (uint32_t)(st * STW + (kk + 8) * BPAD + nq) * 4u,
                   Bb + (size_t)(k0 + kk + 8) * p.ldb + n0 + nq, true);
      }
    }
    cp_commit();
  };

  issue(0, 0);
  issue(1, 1);
  issue(2, 2);

  int cur = 0;
  for (int it = 0; it < nk; it++) {
    cp_wait<STAGES - 2>();  // stage `cur` complete
    __syncthreads();
    issue(it + 3, (cur + 3) & (STAGES - 1));

    const uint32_t* Bsp = Bsm + cur * STW;
#pragma unroll
    for (int ks = 0; ks < 16; ks += 8) {
      uint32_t afr[4][4];
#pragma unroll
      for (int mt = 0; mt < 4; mt++) {
        int row = warp_m * 64 + mt * 16 + lm_row;
        uint32_t saddr =
            as_base + (uint32_t)(cur * STW + row * APAD + ks + lm_col) * 4u;
        ldsm4(afr[mt], saddr);
      }
      uint32_t bfr[4][2];
      if (p.transB) {
#pragma unroll
        for (int nt = 0; nt < 4; nt++) {
          int ncol = warp_n * 32 + nt * 8 + gid;
          bfr[nt][0] = Bsp[ncol * APAD + ks + tig];
          bfr[nt][1] = Bsp[ncol * APAD + ks + tig + 4];
        }
      } else {
#pragma unroll
        for (int nt = 0; nt < 4; nt++) {
          int ncol = warp_n * 32 + nt * 8 + gid;
          bfr[nt][0] = Bsp[(ks + tig) * BPAD + ncol];
          bfr[nt][1] = Bsp[(ks + tig + 4) * BPAD + ncol];
        }
      }
#pragma unroll
      for (int mt = 0; mt < 4; mt++)
#pragma unroll
        for (int nt = 0; nt < 4; nt++) mma_tf32(acc[mt][nt], afr[mt], bfr[nt]);
    }
    cur = (cur + 1) & (STAGES - 1);
  }

  // --- epilogue ---
#pragma unroll
  for (int mt = 0; mt < 4; mt++) {
#pragma unroll
    for (int nt = 0; nt < 4; nt++) {
#pragma unroll
      for (int ee = 0; ee < 4; ee++) {
        int gm = m0 + warp_m * 64 + mt * 16 + gid + (ee >= 2 ? 8 : 0);
        int gn = n0 + warp_n * 32 + nt * 8 + tig * 2 + (ee & 1);
        if (gm >= Meff) continue;
        float v = acc[mt][nt][ee];
        if (p.mode == M_QKV)
          v += p.bias[gn];
        else if (p.mode == M_WO)
          v += p.resid[(size_t)gm * p.ldc + gn];
        else if (p.mode == M_SCORES) {
          if (gn > gm) continue;  // masked region never read
          v *= SCALE;
        }
        Cb[(size_t)gm * p.ldc + gn] = v;
      }
    }
  }
}

// ---------------------------------------------------------------------------
// fp32 SIMT GEMM (kept for the tiny gate GEMM -> exact routing inputs)
// ---------------------------------------------------------------------------
__global__ __launch_bounds__(256) void gemm_kernel(GemmP p) {
  const float* Ab = p.A;
  const float* Bb = p.Bm;
  float* Cb = p.C;
  int Meff = p.M;

  int m0 = blockIdx.y * 64, n0 = blockIdx.x * 64;
  if (m0 >= Meff) return;

  __shared__ float As[16][68];
  __shared__ float Bs[16][68];
  int tid = threadIdx.x, tx = tid & 15, ty = tid >> 4;
  float acc[4][4] = {};

  for (int k0 = 0; k0 < p.K; k0 += 16) {
#pragma unroll
    for (int l = 0; l < 4; l++) {
      int i = tid + l * 256;
      int row = i >> 4, col = i & 15;
      int gm = m0 + row;
      float v = 0.f;
      if (gm < Meff) v = Ab[(size_t)gm * p.lda + k0 + col];
      As[col][row] = v;
    }
#pragma unroll
    for (int l = 0; l < 4; l++) {
      int i = tid + l * 256;
      if (p.transB) {
        int col = i >> 4, kk = i & 15;
        Bs[kk][col] = Bb[(size_t)(n0 + col) * p.ldb + (k0 + kk)];
      } else {
        int kk = i >> 6, col = i & 63;
        Bs[kk][col] = Bb[(size_t)(k0 + kk) * p.ldb + (n0 + col)];
      }
    }
    __syncthreads();
#pragma unroll
    for (int kk = 0; kk < 16; kk++) {
      float4 a4 = *(const float4*)(&As[kk][ty * 4]);
      float4 b4 = *(const float4*)(&Bs[kk][tx * 4]);
      float av[4] = {a4.x, a4.y, a4.z, a4.w};
      float bv[4] = {b4.x, b4.y, b4.z, b4.w};
#pragma unroll
      for (int i = 0; i < 4; i++)
#pragma unroll
        for (int j = 0; j < 4; j++) acc[i][j] += av[i] * bv[j];
    }
    __syncthreads();
  }

#pragma unroll
  for (int i = 0; i < 4; i++) {
    int gm = m0 + ty * 4 + i;
    if (gm >= Meff) continue;
#pragma unroll
    for (int j = 0; j < 4; j++) {
      int gn = n0 + tx * 4 + j;
      Cb[(size_t)gm * p.ldc + gn] = acc[i][j];
    }
  }
}

// ---------------------------------------------------------------------------
// Row softmax, causal-aware: only i<=q is live; zero-fill i>q.
// ---------------------------------------------------------------------------
__global__ void softmax_kernel(float* __restrict__ sc) {
  size_t row = blockIdx.x;
  int q = (int)(row & (S - 1));
  int len = q + 1;
  float* p = sc + row * (size_t)S;
  __shared__ float red[8];
  float mx = -INFINITY;
  for (int i = threadIdx.x; i < len; i += 256) mx = fmaxf(mx, p[i]);
  for (int o = 16; o; o >>= 1) mx = fmaxf(mx, __shfl_xor_sync(~0u, mx, o));
  if ((threadIdx.x & 31) == 0) red[threadIdx.x >> 5] = mx;
  __syncthreads();
  if (threadIdx.x == 0) {
    float m = red[0];
    for (int i = 1; i < 8; i++) m = fmaxf(m, red[i]);
    red[0] = m;
  }
  __syncthreads();
  mx = red[0];
  __syncthreads();
  float sum = 0.f;
  for (int i = threadIdx.x; i < len; i += 256) {
    float e = expf(p[i] - mx);
    p[i] = e;
    sum += e;
  }
  for (int o = 16; o; o >>= 1) sum += __shfl_xor_sync(~0u, sum, o);
  if ((threadIdx.x & 31) == 0) red[threadIdx.x >> 5] = sum;
  __syncthreads();
  if (threadIdx.x == 0) {
    float t = 0.f;
    for (int i = 0; i < 8; i++) t += red[i];
    red[0] = t;
  }
  __syncthreads();
  float inv = 1.f / red[0];
  for (int i = threadIdx.x; i < len; i += 256) p[i] *= inv;
  for (int i = len + threadIdx.x; i < S; i += 256) p[i] = 0.f;
}

// ---------------------------------------------------------------------------
// Routing: grouped top-k with sigmoid gate. 1 thread / token.
// ---------------------------------------------------------------------------
__global__ void route_kernel(const float* __restrict__ logits,
                             const float* __restrict__ gate_b,
                             int* __restrict__ topi, float* __restrict__ fw) {
  int t = blockIdx.x * blockDim.x + threadIdx.x;
  if (t >= T) return;
  float corr[E];
  const float* lg = logits + (size_t)t * E;
  for (int e = 0; e < E; e++) {
    float s = 1.f / (1.f + expf(-lg[e]));
    corr[e] = s + gate_b[e];
  }
  float grp[NG];
  for (int g = 0; g < NG; g++) {
    float m1 = -INFINITY, m2 = -INFINITY;
    for (int i = 0; i < E / NG; i++) {
      float v = corr[g * (E / NG) + i];
      if (v > m1) {
        m2 = m1;
        m1 = v;
      } else if (v > m2) {
        m2 = v;
      }
    }
    grp[g] = m1 + m2;
  }
  unsigned gsel = 0;
  for (int it = 0; it < TG; it++) {
    float best = -INFINITY;
    int bi = 0;
    for (int g = 0; g < NG; g++)
      if (!((gsel >> g) & 1u) && grp[g] > best) {
        best = grp[g];
        bi = g;
      }
    gsel |= 1u << bi;
  }
  unsigned long long esel = 0ull;
  int sel[TK];
  float ws[TK];
  float wsum = 0.f;
  for (int it = 0; it < TK; it++) {
    float best = -INFINITY;
    int bi = 0;
    for (int e = 0; e < E; e++) {
      if (!((gsel >> (e >> 3)) & 1u)) continue;
      if ((esel >> e) & 1ull) continue;
      if (corr[e] > best) {
        best = corr[e];
        bi = e;
      }
    }
    esel |= 1ull << bi;
    sel[it] = bi;
    float s = corr[bi] - gate_b[bi];  // recover sigmoid value
    ws[it] = s;
    wsum += s;
  }
  float inv = 1.f / wsum;
  for (int j = 0; j < TK; j++) {
    topi[t * TK + j] = sel[j];
    fw[t * TK + j] = ws[j] * inv;  // RSF = 1
  }
}

__global__ void zero_cnt_kernel(int* __restrict__ cnt) {
  if (threadIdx.x < E) cnt[threadIdx.x] = 0;
}

__global__ void assign_kernel(const int* __restrict__ topi,
                              int* __restrict__ cnt, int* __restrict__ tok,
                              int* __restrict__ slotpos) {
  int i = blockIdx.x * blockDim.x + threadIdx.x;
  if (i >= T * TK) return;
  int e = topi[i];
  int p = atomicAdd(&cnt[e], 1);
  if (p < CAP) {
    tok[e * CAP + p] = i / TK;
    slotpos[i] = p;
  } else {
    slotpos[i] = -1;
  }
}

// ---------------------------------------------------------------------------
// SiLU-gate activations
// ---------------------------------------------------------------------------
__global__ void moe_act_kernel(const float* __restrict__ gu,
                               float* __restrict__ act,
                               const int* __restrict__ cnt) {
  size_t idx = (size_t)blockIdx.x * 256 + threadIdx.x;
  if (idx >= (size_t)E * CAP * FI) return;
  int e = (int)(idx / ((size_t)CAP * FI));
  int r = (int)(idx % ((size_t)CAP * FI));
  int c = r / FI, f = r % FI;
  if (c >= min(cnt[e], CAP)) return;
  const float* gr = gu + ((size_t)e * CAP + c) * (2 * FI);
  float g = gr[f], u = gr[FI + f];
  act[((size_t)e * CAP + c) * FI + f] = (g / (1.f + expf(-g))) * u;
}

__global__ void shared_act_kernel(const float* __restrict__ sgu,
                                  float* __restrict__ act) {
  size_t idx = (size_t)blockIdx.x * 256 + threadIdx.x;
  if (idx >= (size_t)T * FSH) return;
  int t = (int)(idx / FSH), f = (int)(idx % FSH);
  const float* gr = sgu + (size_t)t * (2 * FSH);
  float g = gr[f], u = gr[FSH + f];
  act[(size_t)t * FSH + f] = (g / (1.f + expf(-g))) * u;
}

// ---------------------------------------------------------------------------
// Final combine: out = h2 + shared + sum_j eo[e_j, pos_j] * w_j
// ---------------------------------------------------------------------------
__global__ void final_kernel(const float* __restrict__ h2,
                             const float* __restrict__ sh,
                             const float* __restrict__ eo,
                             const int* __restrict__ topi,
                             const int* __restrict__ slotpos,
                             const float* __restrict__ fw,
                             float* __restrict__ out) {
  int t = blockIdx.x;
  int sel_e[TK], sel_p[TK];
  float sel_w[TK];
#pragma unroll
  for (int j = 0; j < TK; j++) {
    sel_e[j] = topi[t * TK + j];
    sel_p[j] = slotpos[t * TK + j];
    sel_w[j] = fw[t * TK + j];
  }
  for (int c = threadIdx.x; c < H; c += 256) {
    float v = h2[(size_t)t * H + c] + sh[(size_t)t * H + c];
#pragma unroll
    for (int j = 0; j < TK; j++) {
      if (sel_p[j] >= 0)
        v += eo[((size_t)sel_e[j] * CAP + sel_p[j]) * H + c] * sel_w[j];
    }
    out[(size_t)t * H + c] = v;
  }
}

// ---------------------------------------------------------------------------
// Host launcher
// ---------------------------------------------------------------------------
extern "C" void kernel_launch(void* const* d_in, const int* in_sizes, int n_in,
                              void* d_out, int out_size) {
  const float* x = (const float*)d_in[0];
  const int* positions = (const int*)d_in[1];
  const float* ln1_w = (const float*)d_in[2];
  const float* ln2_w = (const float*)d_in[3];
  const float* wqkv = (const float*)d_in[4];
  const float* bqkv = (const float*)d_in[5];
  const float* qn_w = (const float*)d_in[6];
  const float* kn_w = (const float*)d_in[7];
  const float* wo = (const float*)d_in[8];
  const float* gate_w = (const float*)d_in[9];
  const float* gate_b = (const float*)d_in[10];
  const float* w_gu = (const float*)d_in[11];
  const float* w_dn = (const float*)d_in[12];
  const float* sw_gu = (const float*)d_in[13];
  const float* sw_dn = (const float*)d_in[14];
  float* out = (float*)d_out;

  static bool attr_set = false;
  if (!attr_set) {
    cudaFuncSetAttribute(gemm_tc, cudaFuncAttributeMaxDynamicSharedMemorySize,
                         GEMM_DSMEM);
    attr_set = true;
  }

  float* scr = nullptr;
  cudaGetSymbolAddress((void**)&scr, g_scratch);
  int* topi = nullptr;
  cudaGetSymbolAddress((void**)&topi, g_topi);
  int* slotpos = nullptr;
  cudaGetSymbolAddress((void**)&slotpos, g_slotpos);
  int* cnt = nullptr;
  cudaGetSymbolAddress((void**)&cnt, g_cnt);
  int* tok = nullptr;
  cudaGetSymbolAddress((void**)&tok, g_tok);

  float* bh = scr + OFF_H;
  float* bqkvb = scr + OFF_QKV;
  float* bq = scr + OFF_Q;
  float* bk = scr + OFF_K;
  float* bsc = scr + OFF_SC;
  float* baout = scr + OFF_AOUT;
  float* bh2 = scr + OFF_H2;
  float* bxt = scr + OFF_XT;
  float* blog = scr + OFF_LOG;
  float* bfw = scr + OFF_FW;
  float* bsgu = scr + OFF_SGU;
  float* bshact = scr + OFF_SHACT;
  float* bshared = scr + OFF_SHARED;
  float* bgu = scr + OFF_GU;
  float* bact = scr + OFF_ACT;
  float* beo = scr + OFF_EO;

  // 1. rmsnorm1
  rmsnorm_kernel<<<T, 256>>>(x, ln1_w, bh, H);

  // 2. qkv = h @ wqkv^T + b
  {
    GemmP p{};
    p.mode = M_QKV;
    p.A = bh; p.Bm = wqkv; p.C = bqkvb; p.bias = bqkv;
    p.M = T; p.N = QKVW; p.K = H;
    p.lda = H; p.ldb = H; p.ldc = QKVW; p.transB = 1;
    gemm_tc<<<dim3(QKVW / 128, T / 128, 1), 256, GEMM_DSMEM>>>(p);
  }

  // 3. q/k rmsnorm + rope
  qknorm_rope_kernel<<<dim3(T, NH + NKV), 128>>>(bqkvb, positions, qn_w, kn_w,
                                                 bq, bk);

  // 4. scores = scale * q @ k^T (live region only)
  {
    GemmP p{};
    p.mode = M_SCORES;
    p.A = bq; p.Bm = bk; p.C = bsc;
    p.M = S; p.N = S; p.K = D;
    p.lda = NH * D; p.ldb = NKV * D; p.ldc = S; p.transB = 1;
    gemm_tc<<<dim3(S / 128, S / 128, B * NH), 256, GEMM_DSMEM>>>(p);
  }

  // 5. softmax (causal-aware, zero-fills masked region)
  softmax_kernel<<<B * NH * S, 256>>>(bsc);

  // 6. out = attn @ v
  {
    GemmP p{};
    p.mode = M_AV;
    p.A = bsc; p.Bm = bqkvb; p.C = baout;
    p.M = S; p.N = D; p.K = S;
    p.lda = S; p.ldb = QKVW; p.ldc = NH * D; p.transB = 0;
    gemm_tc<<<dim3(D / 128, S / 128, B * NH), 256, GEMM_DSMEM>>>(p);
  }

  // 7. h2 = x + aout @ wo^T
  {
    GemmP p{};
    p.mode = M_WO;
    p.A = baout; p.Bm = wo; p.C = bh2; p.resid = x;
    p.M = T; p.N = H; p.K = NH * D;
    p.lda = NH * D; p.ldb = NH * D; p.ldc = H; p.transB = 1;
    gemm_tc<<<dim3(H / 128, T / 128, 1), 256, GEMM_DSMEM>>>(p);
  }

  // 8. rmsnorm2
  rmsnorm_kernel<<<T, 256>>>(bh2, ln2_w, bxt, H);

  // 9. gate logits (exact fp32 -> stable routing)
  {
    GemmP p{};
    p.mode = M_GATE;
    p.A = bxt; p.Bm = gate_w; p.C = blog;
    p.M = T; p.N = E; p.K = H;
    p.lda = H; p.ldb = H; p.ldc = E; p.transB = 1;
    gemm_kernel<<<dim3(1, T / 64, 1), 256>>>(p);
  }

  // 10. routing
  route_kernel<<<T / 256, 256>>>(blog, gate_b, topi, bfw);
  zero_cnt_kernel<<<1, 64>>>(cnt);
  assign_kernel<<<(T * TK) / 256, 256>>>(topi, cnt, tok, slotpos);

  // 11. expert gu GEMM (gathered rows)
  {
    GemmP p{};
    p.mode = M_MOEGU;
    p.A = bxt; p.Bm = w_gu; p.C = bgu;
    p.gidx = tok; p.cnt = cnt;
    p.M = CAP; p.N = 2 * FI; p.K = H;
    p.lda = H; p.ldb = 2 * FI; p.ldc = 2 * FI; p.transB = 0;
    gemm_tc<<<dim3((2 * FI) / 128, CAP / 128, E), 256, GEMM_DSMEM>>>(p);
  }

  // 12. silu * up
  moe_act_kernel<<<(int)(((size_t)E * CAP * FI + 255) / 256), 256>>>(bgu, bact,
                                                                     cnt);

  // 13. expert down GEMM
  {
    GemmP p{};
    p.mode = M_MOEDN;
    p.A = bact; p.Bm = w_dn; p.C = beo;
    p.cnt = cnt;
    p.M = CAP; p.N = H; p.K = FI;
    p.lda = FI; p.ldb = H; p.ldc = H; p.transB = 0;
    gemm_tc<<<dim3(H / 128, CAP / 128, E), 256, GEMM_DSMEM>>>(p);
  }

  // 14. shared expert
  {
    GemmP p{};
    p.mode = M_SGU;
    p.A = bxt; p.Bm = sw_gu; p.C = bsgu;
    p.M = T; p.N = 2 * FSH; p.K = H;
    p.lda = H; p.ldb = 2 * FSH; p.ldc = 2 * FSH; p.transB = 0;
    gemm_tc<<<dim3((2 * FSH) / 128, T / 128, 1), 256, GEMM_DSMEM>>>(p);
  }
  shared_act_kernel<<<(int)(((size_t)T * FSH + 255) / 256), 256>>>(bsgu,
                                                                   bshact);
  {
    GemmP p{};
    p.mode = M_SDN;
    p.A = bshact; p.Bm = sw_dn; p.C = bshared;
    p.M = T; p.N = H; p.K = FSH;
    p.lda = FSH; p.ldb = H; p.ldc = H; p.transB = 0;
    gemm_tc<<<dim3(H / 128, T / 128, 1), 256, GEMM_DSMEM>>>(p);
  }

  // 15. combine
  final_kernel<<<T, 256>>>(bh2, bshared, beo, topi, slotpos, bfw, out);
}

// round 6
// speedup vs baseline: 1.1005x; 1.1005x over previous
#include <cuda_runtime.h>
#include <math.h>
#include <stdint.h>

// ---------------------------------------------------------------------------
// Problem constants
// ---------------------------------------------------------------------------
namespace cfg {
constexpr int B = 2, S = 1024, H = 1024;
constexpr int NH = 8, NKV = 2, D = 128, ROT = 64;
constexpr int E = 64, TK = 8, NG = 8, TG = 4;
constexpr int FI = 512, FSH = 512, CAP = 512;
constexpr int T = B * S;                  // 2048 tokens
constexpr int QKVW = (NH + 2 * NKV) * D;  // 1536
constexpr float EPS = 1e-5f;
constexpr float SCALE = 0.08838834764831843f;  // 128^-0.5
constexpr float THETA = 10000.0f;
}  // namespace cfg

using namespace cfg;

// ---------------------------------------------------------------------------
// Static device scratch (no allocations allowed)
// ---------------------------------------------------------------------------
constexpr size_t N_H      = (size_t)T * H;
constexpr size_t N_QKV    = (size_t)T * QKVW;
constexpr size_t N_Q      = (size_t)T * NH * D;
constexpr size_t N_K      = (size_t)T * NKV * D;
constexpr size_t N_SC     = (size_t)B * NH * S * S;
constexpr size_t N_AOUT   = (size_t)T * NH * D;
constexpr size_t N_H2     = (size_t)T * H;
constexpr size_t N_XT     = (size_t)T * H;
constexpr size_t N_LOG    = (size_t)T * E;
constexpr size_t N_FW     = (size_t)T * TK;
constexpr size_t N_SGU    = (size_t)T * 2 * FSH;
constexpr size_t N_SHACT  = (size_t)T * FSH;
constexpr size_t N_COMB   = (size_t)T * H;          // shared + routed accum
constexpr size_t N_ACT    = (size_t)E * CAP * FI;   // expert act

constexpr size_t OFF_H      = 0;
constexpr size_t OFF_QKV    = OFF_H + N_H;
constexpr size_t OFF_Q      = OFF_QKV + N_QKV;
constexpr size_t OFF_K      = OFF_Q + N_Q;
constexpr size_t OFF_SC     = OFF_K + N_K;
constexpr size_t OFF_AOUT   = OFF_SC + N_SC;
constexpr size_t OFF_H2     = OFF_AOUT + N_AOUT;
constexpr size_t OFF_XT     = OFF_H2 + N_H2;
constexpr size_t OFF_LOG    = OFF_XT + N_XT;
constexpr size_t OFF_FW     = OFF_LOG + N_LOG;
constexpr size_t OFF_SGU    = OFF_FW + N_FW;
constexpr size_t OFF_SHACT  = OFF_SGU + N_SGU;
constexpr size_t OFF_COMB   = OFF_SHACT + N_SHACT;
constexpr size_t OFF_ACT    = OFF_COMB + N_COMB;
constexpr size_t SCRATCH_F  = OFF_ACT + N_ACT;

__device__ float g_scratch[SCRATCH_F];

__device__ int g_topi[T * TK];
__device__ int g_cnt[E];
__device__ int g_tok[E * CAP];
__device__ float g_wslot[E * CAP];

// ---------------------------------------------------------------------------
// mma / cp.async helpers
// ---------------------------------------------------------------------------
__device__ __forceinline__ void mma_tf32(float c[4], const uint32_t a[4],
                                         const uint32_t b[2]) {
  asm volatile(
      "mma.sync.aligned.m16n8k8.row.col.f32.tf32.tf32.f32 "
      "{%0,%1,%2,%3}, {%4,%5,%6,%7}, {%8,%9}, {%0,%1,%2,%3};\n"
      : "+f"(c[0]), "+f"(c[1]), "+f"(c[2]), "+f"(c[3])
      : "r"(a[0]), "r"(a[1]), "r"(a[2]), "r"(a[3]), "r"(b[0]), "r"(b[1]));
}

__device__ __forceinline__ void ldsm4(uint32_t r[4], uint32_t saddr) {
  asm volatile(
      "ldmatrix.sync.aligned.m8n8.x4.shared.b16 {%0,%1,%2,%3}, [%4];"
      : "=r"(r[0]), "=r"(r[1]), "=r"(r[2]), "=r"(r[3])
      : "r"(saddr));
}

__device__ __forceinline__ void cp_async16(uint32_t dst, const void* src,
                                           bool pred) {
  int sz = pred ? 16 : 0;
  asm volatile("cp.async.cg.shared.global [%0], [%1], 16, %2;\n" ::"r"(dst),
               "l"(src), "r"(sz));
}
__device__ __forceinline__ void cp_commit() {
  asm volatile("cp.async.commit_group;\n");
}
template <int N>
__device__ __forceinline__ void cp_wait() {
  asm volatile("cp.async.wait_group %0;\n" ::"n"(N));
}

// ---------------------------------------------------------------------------
// RMSNorm over rows of length `dim`
// ---------------------------------------------------------------------------
__global__ void rmsnorm_kernel(const float* __restrict__ in,
                               const float* __restrict__ w,
                               float* __restrict__ out, int dim) {
  int t = blockIdx.x;
  const float* r = in + (size_t)t * dim;
  float s = 0.f;
  for (int i = threadIdx.x; i < dim; i += 256) {
    float v = r[i];
    s += v * v;
  }
  for (int o = 16; o; o >>= 1) s += __shfl_xor_sync(~0u, s, o);
  __shared__ float red[8];
  if ((threadIdx.x & 31) == 0) red[threadIdx.x >> 5] = s;
  __syncthreads();
  if (threadIdx.x == 0) {
    float tt = 0.f;
    for (int i = 0; i < 8; i++) tt += red[i];
    red[0] = tt;
  }
  __syncthreads();
  float inv = rsqrtf(red[0] / (float)dim + EPS);
  for (int i = threadIdx.x; i < dim; i += 256)
    out[(size_t)t * dim + i] = r[i] * inv * w[i];
}

// ---------------------------------------------------------------------------
// Per-head Q/K RMSNorm + RoPE. grid (T, NH+NKV), block D=128
// ---------------------------------------------------------------------------
__global__ void qknorm_rope_kernel(const float* __restrict__ qkv,
                                   const int* __restrict__ positions,
                                   const float* __restrict__ qn,
                                   const float* __restrict__ kn,
                                   float* __restrict__ qout,
                                   float* __restrict__ kout) {
  int t = blockIdx.x, hh = blockIdx.y, d = threadIdx.x;
  const float* src;
  const float* w;
  float* dst;
  if (hh < NH) {
    src = qkv + (size_t)t * QKVW + hh * D;
    w = qn;
    dst = qout + ((size_t)t * NH + hh) * D;
  } else {
    int kv = hh - NH;
    src = qkv + (size_t)t * QKVW + NH * D + kv * D;
    w = kn;
    dst = kout + ((size_t)t * NKV + kv) * D;
  }
  float v = src[d];
  float s = v * v;
  for (int o = 16; o; o >>= 1) s += __shfl_xor_sync(~0u, s, o);
  __shared__ float red[4];
  if ((d & 31) == 0) red[d >> 5] = s;
  __syncthreads();
  float tot = red[0] + red[1] + red[2] + red[3];
  float nv = v * rsqrtf(tot / (float)D + EPS) * w[d];
  __shared__ float sh[128];
  sh[d] = nv;
  __syncthreads();
  int sidx = t & (S - 1);
  float pos = (float)positions[sidx];
  float res;
  if (d < ROT / 2) {
    float ang = pos * powf(THETA, -(float)d / (float)(ROT / 2));
    res = sh[d] * cosf(ang) - sh[d + ROT / 2] * sinf(ang);
  } else if (d < ROT) {
    int i2 = d - ROT / 2;
    float ang = pos * powf(THETA, -(float)i2 / (float)(ROT / 2));
    res = sh[d] * cosf(ang) + sh[d - ROT / 2] * sinf(ang);
  } else {
    res = nv;
  }
  dst[d] = res;
}

// ---------------------------------------------------------------------------
// GEMM modes
// ---------------------------------------------------------------------------
enum GemmMode {
  M_QKV = 0,   // C = A @ B^T + bias
  M_SCORES,    // per (b,h): C = scale * Q @ K^T, causal (masked part unwritten)
  M_AV,        // per (b,h): C = attn @ V  (V strided inside qkv buffer)
  M_WO,        // C = resid + A @ B^T
  M_GATE,      // C = A @ B^T
  M_SGU,       // C = A @ B   (NN)
  M_SDN,       // C = A @ B   (NN)
  M_MOEGU,     // per expert: silu(gathered-A @ Bg) * (gathered-A @ Bu) -> act
  M_MOEDN      // per expert: scatter-accumulate (A @ B) * w into comb[token]
};

struct GemmP {
  int mode;
  const float* A;
  const float* Bm;
  float* C;
  const float* bias;
  const float* resid;
  const int* gidx;     // MOEGU: gather rows; MOEDN: token map
  const int* cnt;
  const float* wslot;  // MOEDN: per-slot combine weight
  int M, N, K, lda, ldb, ldc;
  int transB;
};

// ---------------------------------------------------------------------------
// Tensor-core tf32 GEMM: 128x128x16 block tile, 256 threads (8 warps 2x4),
// warp tile 64x32, 4-stage cp.async ring in dynamic smem, 2 CTAs/SM.
// A smem [m][APAD] via ldmatrix.x4; B smem [n][APAD] (transB) or [k][BPAD].
// MOEGU: B-tile = 64 gate cols + 64 up cols; epilogue fuses SiLU via smem.
// MOEDN: epilogue scatters v*w into comb[token] with atomicAdd.
// ---------------------------------------------------------------------------
constexpr int APAD = 20;   // words
constexpr int BPAD = 136;  // words
constexpr int STAGES = 4;
constexpr int STW = 128 * APAD;                   // 2560 words / operand / stage
constexpr int GEMM_DSMEM = STAGES * 2 * STW * 4;  // 81920 bytes

extern __shared__ uint32_t dynsmem[];

__global__ __launch_bounds__(256, 2) void gemm_tc(GemmP p) {
  int z = blockIdx.z;
  const float* Ab = p.A;
  const float* Bb = p.Bm;
  float* Cb = p.C;
  const int* gidx = nullptr;
  const int* tokz = nullptr;
  const float* wz = nullptr;
  int Meff = p.M;

  if (p.mode == M_SCORES) {
    int b = z >> 3, h = z & 7;
    Ab = p.A + ((size_t)(b * S) * NH + h) * D;
    Bb = p.Bm + ((size_t)(b * S) * NKV + (h >> 2)) * D;
    Cb = p.C + (size_t)z * S * S;
  } else if (p.mode == M_AV) {
    int b = z >> 3, h = z & 7;
    Ab = p.A + (size_t)z * S * S;
    Bb = p.Bm + (size_t)(b * S) * QKVW + (size_t)(NH + NKV) * D + (h >> 2) * D;
    Cb = p.C + (size_t)(b * S) * (NH * D) + h * D;
  } else if (p.mode == M_MOEGU) {
    Meff = min(p.cnt[z], CAP);
    gidx = p.gidx + z * CAP;
    Bb = p.Bm + (size_t)z * H * (2 * FI);
    Cb = p.C + (size_t)z * CAP * FI;  // act base for this expert
  } else if (p.mode == M_MOEDN) {
    Meff = min(p.cnt[z], CAP);
    Ab = p.A + (size_t)z * CAP * FI;
    Bb = p.Bm + (size_t)z * FI * H;
    tokz = p.gidx + z * CAP;
    wz = p.wslot + z * CAP;
    // Cb = p.C (global comb buffer, token-indexed)
  }

  int m0 = blockIdx.y * 128, n0 = blockIdx.x * 128;
  int n0g = blockIdx.x * 64;  // MOEGU fused column base
  if (m0 >= Meff) return;
  if (p.mode == M_SCORES && n0 > m0 + 127) return;

  int kend = p.K;
  if (p.mode == M_AV) kend = min(p.K, m0 + 128);
  int nk = kend >> 4;

  uint32_t* Asm = dynsmem;                 // STAGES * STW
  uint32_t* Bsm = dynsmem + STAGES * STW;  // STAGES * STW

  int tid = threadIdx.x;
  int lane = tid & 31, wid = tid >> 5;
  int warp_m = wid & 1, warp_n = wid >> 1;  // 2 x 4
  int gid = lane >> 2, tig = lane & 3;

  uint32_t as_base = (uint32_t)__cvta_generic_to_shared(Asm);
  uint32_t bs_base = (uint32_t)__cvta_generic_to_shared(Bsm);
  int lm_row = (lane & 15);
  int lm_col = (lane >> 4) << 2;

  float acc[4][4][4];
#pragma unroll
  for (int a = 0; a < 4; a++)
#pragma unroll
    for (int b = 0; b < 4; b++)
#pragma unroll
      for (int c = 0; c < 4; c++) acc[a][b][c] = 0.f;

  // per-thread A copy indices
  int a_row0 = tid >> 2, a_kq = (tid & 3) * 4;
  const float* a_src0;
  const float* a_src1;
  {
    int gm0 = m0 + a_row0, gm1 = m0 + a_row0 + 64;
    a_src0 = (gm0 < Meff)
                 ? (gidx ? Ab + (size_t)gidx[gm0] * p.lda
                         : Ab + (size_t)gm0 * p.lda)
                 : Ab;
    a_src1 = (gm1 < Meff)
                 ? (gidx ? Ab + (size_t)gidx[gm1] * p.lda
                         : Ab + (size_t)gm1 * p.lda)
                 : Ab;
  }
  bool a_v0 = (m0 + a_row0) < Meff;
  bool a_v1 = (m0 + a_row0 + 64) < Meff;

  auto issue = [&](int it, int st) {
    if (it < nk) {
      int k0 = it << 4;
      cp_async16(as_base + (uint32_t)(st * STW + a_row0 * APAD + a_kq) * 4u,
                 a_src0 + k0 + a_kq, a_v0);
      cp_async16(
          as_base + (uint32_t)(st * STW + (a_row0 + 64) * APAD + a_kq) * 4u,
          a_src1 + k0 + a_kq, a_v1);
      if (p.mode == M_MOEGU) {
        // fused gate/up: 16 k-rows x (64 gate + 64 up) cols
#pragma unroll
        for (int l = 0; l < 2; l++) {
          int c = tid + l * 256;         // 0..511 chunks of 16B
          int kk = c >> 5;               // 0..15
          int w = c & 31;                // chunk within row
          int half = w >> 4;             // 0 = gate, 1 = up
          int off4 = (w & 15) * 4;       // 0..60
          cp_async16(bs_base + (uint32_t)(st * STW + kk * BPAD + half * 64 +
                                          off4) * 4u,
                     Bb + (size_t)(k0 + kk) * p.ldb + half * FI + n0g + off4,
                     true);
        }
      } else if (p.transB) {
        int n = tid >> 2, kq = (tid & 3) * 4;
        cp_async16(bs_base + (uint32_t)(st * STW + n * APAD + kq) * 4u,
                   Bb + (size_t)(n0 + n) * p.ldb + k0 + kq, true);
        cp_async16(bs_base + (uint32_t)(st * STW + (n + 64) * APAD + kq) * 4u,
                   Bb + (size_t)(n0 + n + 64) * p.ldb + k0 + kq, true);
      } else {
        int kk = tid >> 5, nq = (tid & 31) * 4;
        cp_async16(bs_base + (uint32_t)(st * STW + kk * BPAD + nq) * 4u,
                   Bb + (size_t)(k0 + kk) * p.ldb + n0 + nq, true);
        cp_async16(bs_base + (uint32_t)(st * STW + (kk + 8) * BPAD + nq) * 4u,
                   Bb + (size_t)(k0 + kk + 8) * p.ldb + n0 + nq, true);
      }
    }
    cp_commit();
  };

  issue(0, 0);
  issue(1, 1);
  issue(2, 2);

  int cur = 0;
  for (int it = 0; it < nk; it++) {
    cp_wait<STAGES - 2>();
    __syncthreads();
    issue(it + 3, (cur + 3) & (STAGES - 1));

    const uint32_t* Bsp = Bsm + cur * STW;
#pragma unroll
    for (int ks = 0; ks < 16; ks += 8) {
      uint32_t afr[4][4];
#pragma unroll
      for (int mt = 0; mt < 4; mt++) {
        int row = warp_m * 64 + mt * 16 + lm_row;
        uint32_t saddr =
            as_base + (uint32_t)(cur * STW + row * APAD + ks + lm_col) * 4u;
        ldsm4(afr[mt], saddr);
      }
      uint32_t bfr[4][2];
      if (p.transB) {
#pragma unroll
        for (int nt = 0; nt < 4; nt++) {
          int ncol = warp_n * 32 + nt * 8 + gid;
          bfr[nt][0] = Bsp[ncol * APAD + ks + tig];
          bfr[nt][1] = Bsp[ncol * APAD + ks + tig + 4];
        }
      } else {
#pragma unroll
        for (int nt = 0; nt < 4; nt++) {
          int ncol = warp_n * 32 + nt * 8 + gid;
          bfr[nt][0] = Bsp[(ks + tig) * BPAD + ncol];
          bfr[nt][1] = Bsp[(ks + tig + 4) * BPAD + ncol];
        }
      }
#pragma unroll
      for (int mt = 0; mt < 4; mt++)
#pragma unroll
        for (int nt = 0; nt < 4; nt++) mma_tf32(acc[mt][nt], afr[mt], bfr[nt]);
    }
    cur = (cur + 1) & (STAGES - 1);
  }

  // --- epilogues ---
  if (p.mode == M_MOEGU) {
    // exchange through smem, fuse SiLU, write act directly
    cp_wait<0>();
    __syncthreads();
    float* Cs = (float*)dynsmem;  // 128 x 132 floats
#pragma unroll
    for (int mt = 0; mt < 4; mt++)
#pragma unroll
      for (int nt = 0; nt < 4; nt++)
#pragma unroll
        for (int ee = 0; ee < 4; ee++) {
          int r = warp_m * 64 + mt * 16 + gid + (ee >= 2 ? 8 : 0);
          int c = warp_n * 32 + nt * 8 + tig * 2 + (ee & 1);
          Cs[r * 132 + c] = acc[mt][nt][ee];
        }
    __syncthreads();
    for (int i = tid; i < 128 * 64; i += 256) {
      int r = i >> 6, c = i & 63;
      int gm = m0 + r;
      if (gm < Meff) {
        float g = Cs[r * 132 + c];
        float u = Cs[r * 132 + 64 + c];
        float a = (g / (1.f + expf(-g))) * u;
        Cb[(size_t)gm * FI + n0g + c] = a;
      }
    }
    return;
  }

  if (p.mode == M_MOEDN) {
    // scatter-accumulate into comb[token]
#pragma unroll
    for (int mt = 0; mt < 4; mt++) {
#pragma unroll
      for (int nt = 0; nt < 4; nt++) {
#pragma unroll
        for (int ee = 0; ee < 4; ee++) {
          int gm = m0 + warp_m * 64 + mt * 16 + gid + (ee >= 2 ? 8 : 0);
          if (gm >= Meff) continue;
          int gn = n0 + warp_n * 32 + nt * 8 + tig * 2 + (ee & 1);
          int t = tokz[gm];
          float w = wz[gm];
          atomicAdd(&Cb[(size_t)t * p.ldc + gn], acc[mt][nt][ee] * w);
        }
      }
    }
    return;
  }

#pragma unroll
  for (int mt = 0; mt < 4; mt++) {
#pragma unroll
    for (int nt = 0; nt < 4; nt++) {
#pragma unroll
      for (int ee = 0; ee < 4; ee++) {
        int gm = m0 + warp_m * 64 + mt * 16 + gid + (ee >= 2 ? 8 : 0);
        int gn = n0 + warp_n * 32 + nt * 8 + tig * 2 + (ee & 1);
        if (gm >= Meff) continue;
        float v = acc[mt][nt][ee];
        if (p.mode == M_QKV)
          v += p.bias[gn];
        else if (p.mode == M_WO)
          v += p.resid[(size_t)gm * p.ldc + gn];
        else if (p.mode == M_SCORES) {
          if (gn > gm) continue;
          v *= SCALE;
        }
        Cb[(size_t)gm * p.ldc + gn] = v;
      }
    }
  }
}

// ---------------------------------------------------------------------------
// fp32 SIMT GEMM (kept for the tiny gate GEMM -> exact routing inputs)
// ---------------------------------------------------------------------------
__global__ __launch_bounds__(256) void gemm_kernel(GemmP p) {
  const float* Ab = p.A;
  const float* Bb = p.Bm;
  float* Cb = p.C;
  int Meff = p.M;

  int m0 = blockIdx.y * 64, n0 = blockIdx.x * 64;
  if (m0 >= Meff) return;

  __shared__ float As[16][68];
  __shared__ float Bs[16][68];
  int tid = threadIdx.x, tx = tid & 15, ty = tid >> 4;
  float acc[4][4] = {};

  for (int k0 = 0; k0 < p.K; k0 += 16) {
#pragma unroll
    for (int l = 0; l < 4; l++) {
      int i = tid + l * 256;
      int row = i >> 4, col = i & 15;
      int gm = m0 + row;
      float v = 0.f;
      if (gm < Meff) v = Ab[(size_t)gm * p.lda + k0 + col];
      As[col][row] = v;
    }
#pragma unroll
    for (int l = 0; l < 4; l++) {
      int i = tid + l * 256;
      if (p.transB) {
        int col = i >> 4, kk = i & 15;
        Bs[kk][col] = Bb[(size_t)(n0 + col) * p.ldb + (k0 + kk)];
      } else {
        int kk = i >> 6, col = i & 63;
        Bs[kk][col] = Bb[(size_t)(k0 + kk) * p.ldb + (n0 + col)];
      }
    }
    __syncthreads();
#pragma unroll
    for (int kk = 0; kk < 16; kk++) {
      float4 a4 = *(const float4*)(&As[kk][ty * 4]);
      float4 b4 = *(const float4*)(&Bs[kk][tx * 4]);
      float av[4] = {a4.x, a4.y, a4.z, a4.w};
      float bv[4] = {b4.x, b4.y, b4.z, b4.w};
#pragma unroll
      for (int i = 0; i < 4; i++)
#pragma unroll
        for (int j = 0; j < 4; j++) acc[i][j] += av[i] * bv[j];
    }
    __syncthreads();
  }

#pragma unroll
  for (int i = 0; i < 4; i++) {
    int gm = m0 + ty * 4 + i;
    if (gm >= Meff) continue;
#pragma unroll
    for (int j = 0; j < 4; j++) {
      int gn = n0 + tx * 4 + j;
      Cb[(size_t)gm * p.ldc + gn] = acc[i][j];
    }
  }
}

// ---------------------------------------------------------------------------
// Row softmax, causal-aware: only i<=q live; zero-fill only diagonal block.
// ---------------------------------------------------------------------------
__global__ void softmax_kernel(float* __restrict__ sc) {
  size_t row = blockIdx.x;
  int q = (int)(row & (S - 1));
  int len = q + 1;
  int fill_end = ((q >> 7) + 1) << 7;  // AV never reads past this
  float* p = sc + row * (size_t)S;
  __shared__ float red[8];
  float mx = -INFINITY;
  for (int i = threadIdx.x; i < len; i += 256) mx = fmaxf(mx, p[i]);
  for (int o = 16; o; o >>= 1) mx = fmaxf(mx, __shfl_xor_sync(~0u, mx, o));
  if ((threadIdx.x & 31) == 0) red[threadIdx.x >> 5] = mx;
  __syncthreads();
  if (threadIdx.x == 0) {
    float m = red[0];
    for (int i = 1; i < 8; i++) m = fmaxf(m, red[i]);
    red[0] = m;
  }
  __syncthreads();
  mx = red[0];
  __syncthreads();
  float sum = 0.f;
  for (int i = threadIdx.x; i < len; i += 256) {
    float e = expf(p[i] - mx);
    p[i] = e;
    sum += e;
  }
  for (int o = 16; o; o >>= 1) sum += __shfl_xor_sync(~0u, sum, o);
  if ((threadIdx.x & 31) == 0) red[threadIdx.x >> 5] = sum;
  __syncthreads();
  if (threadIdx.x == 0) {
    float t = 0.f;
    for (int i = 0; i < 8; i++) t += red[i];
    red[0] = t;
  }
  __syncthreads();
  float inv = 1.f / red[0];
  for (int i = threadIdx.x; i < len; i += 256) p[i] *= inv;
  for (int i = len + threadIdx.x; i < fill_end; i += 256) p[i] = 0.f;
}

// ---------------------------------------------------------------------------
// Routing: grouped top-k with sigmoid gate. 1 thread / token.
// ---------------------------------------------------------------------------
__global__ void route_kernel(const float* __restrict__ logits,
                             const float* __restrict__ gate_b,
                             int* __restrict__ topi, float* __restrict__ fw) {
  int t = blockIdx.x * blockDim.x + threadIdx.x;
  if (t >= T) return;
  float corr[E];
  const float* lg = logits + (size_t)t * E;
  for (int e = 0; e < E; e++) {
    float s = 1.f / (1.f + expf(-lg[e]));
    corr[e] = s + gate_b[e];
  }
  float grp[NG];
  for (int g = 0; g < NG; g++) {
    float m1 = -INFINITY, m2 = -INFINITY;
    for (int i = 0; i < E / NG; i++) {
      float v = corr[g * (E / NG) + i];
      if (v > m1) {
        m2 = m1;
        m1 = v;
      } else if (v > m2) {
        m2 = v;
      }
    }
    grp[g] = m1 + m2;
  }
  unsigned gsel = 0;
  for (int it = 0; it < TG; it++) {
    float best = -INFINITY;
    int bi = 0;
    for (int g = 0; g < NG; g++)
      if (!((gsel >> g) & 1u) && grp[g] > best) {
        best = grp[g];
        bi = g;
      }
    gsel |= 1u << bi;
  }
  unsigned long long esel = 0ull;
  int sel[TK];
  float ws[TK];
  float wsum = 0.f;
  for (int it = 0; it < TK; it++) {
    float best = -INFINITY;
    int bi = 0;
    for (int e = 0; e < E; e++) {
      if (!((gsel >> (e >> 3)) & 1u)) continue;
      if ((esel >> e) & 1ull) continue;
      if (corr[e] > best) {
        best = corr[e];
        bi = e;
      }
    }
    esel |= 1ull << bi;
    sel[it] = bi;
    float s = corr[bi] - gate_b[bi];
    ws[it] = s;
    wsum += s;
  }
  float inv = 1.f / wsum;
  for (int j = 0; j < TK; j++) {
    topi[t * TK + j] = sel[j];
    fw[t * TK + j] = ws[j] * inv;  // RSF = 1
  }
}

__global__ void zero_cnt_kernel(int* __restrict__ cnt) {
  if (threadIdx.x < E) cnt[threadIdx.x] = 0;
}

__global__ void assign_kernel(const int* __restrict__ topi,
                              const float* __restrict__ fw,
                              int* __restrict__ cnt, int* __restrict__ tok,
                              float* __restrict__ wslot) {
  int i = blockIdx.x * blockDim.x + threadIdx.x;
  if (i >= T * TK) return;
  int e = topi[i];
  int p = atomicAdd(&cnt[e], 1);
  if (p < CAP) {
    tok[e * CAP + p] = i / TK;
    wslot[e * CAP + p] = fw[i];
  }
}

// ---------------------------------------------------------------------------
// shared expert SiLU
// ---------------------------------------------------------------------------
__global__ void shared_act_kernel(const float* __restrict__ sgu,
                                  float* __restrict__ act) {
  size_t idx = (size_t)blockIdx.x * 256 + threadIdx.x;
  if (idx >= (size_t)T * FSH) return;
  int t = (int)(idx / FSH), f = (int)(idx % FSH);
  const float* gr = sgu + (size_t)t * (2 * FSH);
  float g = gr[f], u = gr[FSH + f];
  act[(size_t)t * FSH + f] = (g / (1.f + expf(-g))) * u;
}

// ---------------------------------------------------------------------------
// Final: out = h2 + comb  (comb = shared expert + scattered routed experts)
// ---------------------------------------------------------------------------
__global__ void final_kernel(const float* __restrict__ h2,
                             const float* __restrict__ comb,
                             float* __restrict__ out) {
  size_t i = (size_t)blockIdx.x * 256 + threadIdx.x;
  if (i < (size_t)T * H) out[i] = h2[i] + comb[i];
}

// ---------------------------------------------------------------------------
// Host launcher
// ---------------------------------------------------------------------------
extern "C" void kernel_launch(void* const* d_in, const int* in_sizes, int n_in,
                              void* d_out, int out_size) {
  const float* x = (const float*)d_in[0];
  const int* positions = (const int*)d_in[1];
  const float* ln1_w = (const float*)d_in[2];
  const float* ln2_w = (const float*)d_in[3];
  const float* wqkv = (const float*)d_in[4];
  const float* bqkv = (const float*)d_in[5];
  const float* qn_w = (const float*)d_in[6];
  const float* kn_w = (const float*)d_in[7];
  const float* wo = (const float*)d_in[8];
  const float* gate_w = (const float*)d_in[9];
  const float* gate_b = (const float*)d_in[10];
  const float* w_gu = (const float*)d_in[11];
  const float* w_dn = (const float*)d_in[12];
  const float* sw_gu = (const float*)d_in[13];
  const float* sw_dn = (const float*)d_in[14];
  float* out = (float*)d_out;

  static bool attr_set = false;
  if (!attr_set) {
    cudaFuncSetAttribute(gemm_tc, cudaFuncAttributeMaxDynamicSharedMemorySize,
                         GEMM_DSMEM);
    attr_set = true;
  }

  float* scr = nullptr;
  cudaGetSymbolAddress((void**)&scr, g_scratch);
  int* topi = nullptr;
  cudaGetSymbolAddress((void**)&topi, g_topi);
  int* cnt = nullptr;
  cudaGetSymbolAddress((void**)&cnt, g_cnt);
  int* tok = nullptr;
  cudaGetSymbolAddress((void**)&tok, g_tok);
  float* wslot = nullptr;
  cudaGetSymbolAddress((void**)&wslot, g_wslot);

  float* bh = scr + OFF_H;
  float* bqkvb = scr + OFF_QKV;
  float* bq = scr + OFF_Q;
  float* bk = scr + OFF_K;
  float* bsc = scr + OFF_SC;
  float* baout = scr + OFF_AOUT;
  float* bh2 = scr + OFF_H2;
  float* bxt = scr + OFF_XT;
  float* blog = scr + OFF_LOG;
  float* bfw = scr + OFF_FW;
  float* bsgu = scr + OFF_SGU;
  float* bshact = scr + OFF_SHACT;
  float* bcomb = scr + OFF_COMB;
  float* bact = scr + OFF_ACT;

  // 1. rmsnorm1
  rmsnorm_kernel<<<T, 256>>>(x, ln1_w, bh, H);

  // 2. qkv = h @ wqkv^T + b
  {
    GemmP p{};
    p.mode = M_QKV;
    p.A = bh; p.Bm = wqkv; p.C = bqkvb; p.bias = bqkv;
    p.M = T; p.N = QKVW; p.K = H;
    p.lda = H; p.ldb = H; p.ldc = QKVW; p.transB = 1;
    gemm_tc<<<dim3(QKVW / 128, T / 128, 1), 256, GEMM_DSMEM>>>(p);
  }

  // 3. q/k rmsnorm + rope
  qknorm_rope_kernel<<<dim3(T, NH + NKV), 128>>>(bqkvb, positions, qn_w, kn_w,
                                                 bq, bk);

  // 4. scores = scale * q @ k^T (live region only)
  {
    GemmP p{};
    p.mode = M_SCORES;
    p.A = bq; p.Bm = bk; p.C = bsc;
    p.M = S; p.N = S; p.K = D;
    p.lda = NH * D; p.ldb = NKV * D; p.ldc = S; p.transB = 1;
    gemm_tc<<<dim3(S / 128, S / 128, B * NH), 256, GEMM_DSMEM>>>(p);
  }

  // 5. softmax (causal-aware, zero-fills only diagonal block remainder)
  softmax_kernel<<<B * NH * S, 256>>>(bsc);

  // 6. out = attn @ v
  {
    GemmP p{};
    p.mode = M_AV;
    p.A = bsc; p.Bm = bqkvb; p.C = baout;
    p.M = S; p.N = D; p.K = S;
    p.lda = S; p.ldb = QKVW; p.ldc = NH * D; p.transB = 0;
    gemm_tc<<<dim3(D / 128, S / 128, B * NH), 256, GEMM_DSMEM>>>(p);
  }

  // 7. h2 = x + aout @ wo^T
  {
    GemmP p{};
    p.mode = M_WO;
    p.A = baout; p.Bm = wo; p.C = bh2; p.resid = x;
    p.M = T; p.N = H; p.K = NH * D;
    p.lda = NH * D; p.ldb = NH * D; p.ldc = H; p.transB = 1;
    gemm_tc<<<dim3(H / 128, T / 128, 1), 256, GEMM_DSMEM>>>(p);
  }

  // 8. rmsnorm2
  rmsnorm_kernel<<<T, 256>>>(bh2, ln2_w, bxt, H);

  // 9. gate logits (exact fp32 -> stable routing)
  {
    GemmP p{};
    p.mode = M_GATE;
    p.A = bxt; p.Bm = gate_w; p.C = blog;
    p.M = T; p.N = E; p.K = H;
    p.lda = H; p.ldb = H; p.ldc = E; p.transB = 1;
    gemm_kernel<<<dim3(1, T / 64, 1), 256>>>(p);
  }

  // 10. routing
  route_kernel<<<T / 256, 256>>>(blog, gate_b, topi, bfw);
  zero_cnt_kernel<<<1, 64>>>(cnt);
  assign_kernel<<<(T * TK) / 256, 256>>>(topi, bfw, cnt, tok, wslot);

  // 11. shared expert -> bcomb (must precede MoE scatter)
  {
    GemmP p{};
    p.mode = M_SGU;
    p.A = bxt; p.Bm = sw_gu; p.C = bsgu;
    p.M = T; p.N = 2 * FSH; p.K = H;
    p.lda = H; p.ldb = 2 * FSH; p.ldc = 2 * FSH; p.transB = 0;
    gemm_tc<<<dim3((2 * FSH) / 128, T / 128, 1), 256, GEMM_DSMEM>>>(p);
  }
  shared_act_kernel<<<(int)(((size_t)T * FSH + 255) / 256), 256>>>(bsgu,
                                                                   bshact);
  {
    GemmP p{};
    p.mode = M_SDN;
    p.A = bshact; p.Bm = sw_dn; p.C = bcomb;
    p.M = T; p.N = H; p.K = FSH;
    p.lda = FSH; p.ldb = H; p.ldc = H; p.transB = 0;
    gemm_tc<<<dim3(H / 128, T / 128, 1), 256, GEMM_DSMEM>>>(p);
  }

  // 12. expert up-gate GEMM fused with SiLU -> bact
  {
    GemmP p{};
    p.mode = M_MOEGU;
    p.A = bxt; p.Bm = w_gu; p.C = bact;
    p.gidx = tok; p.cnt = cnt;
    p.M = CAP; p.N = 128; p.K = H;
    p.lda = H; p.ldb = 2 * FI; p.ldc = FI; p.transB = 0;
    gemm_tc<<<dim3(FI / 64, CAP / 128, E), 256, GEMM_DSMEM>>>(p);
  }

  // 13. expert down GEMM, scatter-accumulate into bcomb
  {
    GemmP p{};
    p.mode = M_MOEDN;
    p.A = bact; p.Bm = w_dn; p.C = bcomb;
    p.gidx = tok; p.cnt = cnt; p.wslot = wslot;
    p.M = CAP; p.N = H; p.K = FI;
    p.lda = FI; p.ldb = H; p.ldc = H; p.transB = 0;
    gemm_tc<<<dim3(H / 128, CAP / 128, E), 256, GEMM_DSMEM>>>(p);
  }

  // 14. out = h2 + comb
  final_kernel<<<(int)(((size_t)T * H + 255) / 256), 256>>>(bh2, bcomb, out);
}

// round 8
// speedup vs baseline: 1.1736x; 1.0664x over previous
#include <cuda_runtime.h>
#include <cuda_fp16.h>
#include <math.h>
#include <stdint.h>

// ---------------------------------------------------------------------------
// Problem constants
// ---------------------------------------------------------------------------
namespace cfg {
constexpr int B = 2, S = 1024, H = 1024;
constexpr int NH = 8, NKV = 2, D = 128, ROT = 64;
constexpr int E = 64, TK = 8, NG = 8, TG = 4;
constexpr int FI = 512, FSH = 512, CAP = 512;
constexpr int T = B * S;                  // 2048 tokens
constexpr int QKVW = (NH + 2 * NKV) * D;  // 1536
constexpr float EPS = 1e-5f;
constexpr float SCALE = 0.08838834764831843f;  // 128^-0.5
constexpr float THETA = 10000.0f;
}  // namespace cfg

using namespace cfg;

// ---------------------------------------------------------------------------
// Static device scratch (no allocations allowed)
// ---------------------------------------------------------------------------
constexpr size_t N_H      = (size_t)T * H;
constexpr size_t N_QKV    = (size_t)T * QKVW;
constexpr size_t N_Q      = (size_t)T * NH * D;
constexpr size_t N_K      = (size_t)T * NKV * D;
constexpr size_t N_SC     = (size_t)B * NH * S * S;
constexpr size_t N_AOUT   = (size_t)T * NH * D;
constexpr size_t N_H2     = (size_t)T * H;
constexpr size_t N_XT     = (size_t)T * H;
constexpr size_t N_LOG    = (size_t)T * E;
constexpr size_t N_FW     = (size_t)T * TK;
constexpr size_t N_SGU    = (size_t)T * 2 * FSH;
constexpr size_t N_SHACT  = (size_t)T * FSH;
constexpr size_t N_COMB   = (size_t)T * H;

constexpr size_t OFF_H      = 0;
constexpr size_t OFF_QKV    = OFF_H + N_H;
constexpr size_t OFF_Q      = OFF_QKV + N_QKV;
constexpr size_t OFF_K      = OFF_Q + N_Q;
constexpr size_t OFF_SC     = OFF_K + N_K;
constexpr size_t OFF_AOUT   = OFF_SC + N_SC;
constexpr size_t OFF_H2     = OFF_AOUT + N_AOUT;
constexpr size_t OFF_XT     = OFF_H2 + N_H2;
constexpr size_t OFF_LOG    = OFF_XT + N_XT;
constexpr size_t OFF_FW     = OFF_LOG + N_LOG;
constexpr size_t OFF_SGU    = OFF_FW + N_FW;
constexpr size_t OFF_SHACT  = OFF_SGU + N_SGU;
constexpr size_t OFF_COMB   = OFF_SHACT + N_SHACT;
constexpr size_t SCRATCH_F  = OFF_COMB + N_COMB;

__device__ float g_scratch[SCRATCH_F];
__device__ __half g_xt16[(size_t)T * H];
__device__ __half g_act16[(size_t)E * CAP * FI];

__device__ int g_topi[T * TK];
__device__ int g_cnt[E];
__device__ int g_tok[E * CAP];
__device__ float g_wslot[E * CAP];

// ---------------------------------------------------------------------------
// mma / cp.async helpers
// ---------------------------------------------------------------------------
__device__ __forceinline__ uint32_t h2u(__half2 h) {
  return *reinterpret_cast<uint32_t*>(&h);
}

__device__ __forceinline__ void mma_tf32(float c[4], const uint32_t a[4],
                                         const uint32_t b[2]) {
  asm volatile(
      "mma.sync.aligned.m16n8k8.row.col.f32.tf32.tf32.f32 "
      "{%0,%1,%2,%3}, {%4,%5,%6,%7}, {%8,%9}, {%0,%1,%2,%3};\n"
      : "+f"(c[0]), "+f"(c[1]), "+f"(c[2]), "+f"(c[3])
      : "r"(a[0]), "r"(a[1]), "r"(a[2]), "r"(a[3]), "r"(b[0]), "r"(b[1]));
}

__device__ __forceinline__ void mma_f16(float c[4], const uint32_t a[4],
                                        const uint32_t b[2]) {
  asm volatile(
      "mma.sync.aligned.m16n8k16.row.col.f32.f16.f16.f32 "
      "{%0,%1,%2,%3}, {%4,%5,%6,%7}, {%8,%9}, {%0,%1,%2,%3};\n"
      : "+f"(c[0]), "+f"(c[1]), "+f"(c[2]), "+f"(c[3])
      : "r"(a[0]), "r"(a[1]), "r"(a[2]), "r"(a[3]), "r"(b[0]), "r"(b[1]));
}

__device__ __forceinline__ void ldsm4(uint32_t r[4], uint32_t saddr) {
  asm volatile(
      "ldmatrix.sync.aligned.m8n8.x4.shared.b16 {%0,%1,%2,%3}, [%4];"
      : "=r"(r[0]), "=r"(r[1]), "=r"(r[2]), "=r"(r[3])
      : "r"(saddr));
}

__device__ __forceinline__ void cp_async16(uint32_t dst, const void* src,
                                           bool pred) {
  int sz = pred ? 16 : 0;
  asm volatile("cp.async.cg.shared.global [%0], [%1], 16, %2;\n" ::"r"(dst),
               "l"(src), "r"(sz));
}
__device__ __forceinline__ void cp_commit() {
  asm volatile("cp.async.commit_group;\n");
}
template <int N>
__device__ __forceinline__ void cp_wait() {
  asm volatile("cp.async.wait_group %0;\n" ::"n"(N));
}

// ---------------------------------------------------------------------------
// RMSNorm over rows of length `dim` (optional packed fp16 second output)
// ---------------------------------------------------------------------------
__global__ void rmsnorm_kernel(const float* __restrict__ in,
                               const float* __restrict__ w,
                               float* __restrict__ out,
                               __half* __restrict__ out16, int dim) {
  int t = blockIdx.x;
  const float* r = in + (size_t)t * dim;
  float s = 0.f;
  for (int i = threadIdx.x; i < dim; i += 256) {
    float v = r[i];
    s += v * v;
  }
  for (int o = 16; o; o >>= 1) s += __shfl_xor_sync(~0u, s, o);
  __shared__ float red[8];
  if ((threadIdx.x & 31) == 0) red[threadIdx.x >> 5] = s;
  __syncthreads();
  if (threadIdx.x == 0) {
    float tt = 0.f;
    for (int i = 0; i < 8; i++) tt += red[i];
    red[0] = tt;
  }
  __syncthreads();
  float inv = rsqrtf(red[0] / (float)dim + EPS);
  for (int i = threadIdx.x * 2; i < dim; i += 512) {
    float v0 = r[i] * inv * w[i];
    float v1 = r[i + 1] * inv * w[i + 1];
    out[(size_t)t * dim + i] = v0;
    out[(size_t)t * dim + i + 1] = v1;
    if (out16) {
      __half2 h = __floats2half2_rn(v0, v1);
      *(__half2*)&out16[(size_t)t * dim + i] = h;
    }
  }
}

// ---------------------------------------------------------------------------
// Per-head Q/K RMSNorm + RoPE. grid (T, NH+NKV), block D=128
// ---------------------------------------------------------------------------
__global__ void qknorm_rope_kernel(const float* __restrict__ qkv,
                                   const int* __restrict__ positions,
                                   const float* __restrict__ qn,
                                   const float* __restrict__ kn,
                                   float* __restrict__ qout,
                                   float* __restrict__ kout) {
  int t = blockIdx.x, hh = blockIdx.y, d = threadIdx.x;
  const float* src;
  const float* w;
  float* dst;
  if (hh < NH) {
    src = qkv + (size_t)t * QKVW + hh * D;
    w = qn;
    dst = qout + ((size_t)t * NH + hh) * D;
  } else {
    int kv = hh - NH;
    src = qkv + (size_t)t * QKVW + NH * D + kv * D;
    w = kn;
    dst = kout + ((size_t)t * NKV + kv) * D;
  }
  float v = src[d];
  float s = v * v;
  for (int o = 16; o; o >>= 1) s += __shfl_xor_sync(~0u, s, o);
  __shared__ float red[4];
  if ((d & 31) == 0) red[d >> 5] = s;
  __syncthreads();
  float tot = red[0] + red[1] + red[2] + red[3];
  float nv = v * rsqrtf(tot / (float)D + EPS) * w[d];
  __shared__ float sh[128];
  sh[d] = nv;
  __syncthreads();
  int sidx = t & (S - 1);
  float pos = (float)positions[sidx];
  float res;
  if (d < ROT / 2) {
    float ang = pos * powf(THETA, -(float)d / (float)(ROT / 2));
    res = sh[d] * cosf(ang) - sh[d + ROT / 2] * sinf(ang);
  } else if (d < ROT) {
    int i2 = d - ROT / 2;
    float ang = pos * powf(THETA, -(float)i2 / (float)(ROT / 2));
    res = sh[d] * cosf(ang) + sh[d - ROT / 2] * sinf(ang);
  } else {
    res = nv;
  }
  dst[d] = res;
}

// ---------------------------------------------------------------------------
// GEMM modes (tf32 path)
// ---------------------------------------------------------------------------
enum GemmMode {
  M_QKV = 0,
  M_SCORES,
  M_AV,
  M_WO,
  M_GATE,
  M_SGU,
  M_SDN
};

struct GemmP {
  int mode;
  const float* A;
  const float* Bm;
  float* C;
  const float* bias;
  const float* resid;
  int M, N, K, lda, ldb, ldc;
  int transB;
};

// ---------------------------------------------------------------------------
// tf32 GEMM (attention + dense projections)
// ---------------------------------------------------------------------------
constexpr int APAD = 20;
constexpr int BPAD = 136;
constexpr int STAGES = 4;
constexpr int STW = 128 * APAD;
constexpr int GEMM_DSMEM = STAGES * 2 * STW * 4;

extern __shared__ uint32_t dynsmem[];

__global__ __launch_bounds__(256, 2) void gemm_tc(GemmP p) {
  int z = blockIdx.z;
  const float* Ab = p.A;
  const float* Bb = p.Bm;
  float* Cb = p.C;
  int Meff = p.M;

  if (p.mode == M_SCORES) {
    int b = z >> 3, h = z & 7;
    Ab = p.A + ((size_t)(b * S) * NH + h) * D;
    Bb = p.Bm + ((size_t)(b * S) * NKV + (h >> 2)) * D;
    Cb = p.C + (size_t)z * S * S;
  } else if (p.mode == M_AV) {
    int b = z >> 3, h = z & 7;
    Ab = p.A + (size_t)z * S * S;
    Bb = p.Bm + (size_t)(b * S) * QKVW + (size_t)(NH + NKV) * D + (h >> 2) * D;
    Cb = p.C + (size_t)(b * S) * (NH * D) + h * D;
  }

  int m0 = blockIdx.y * 128, n0 = blockIdx.x * 128;
  if (m0 >= Meff) return;
  if (p.mode == M_SCORES && n0 > m0 + 127) return;

  int kend = p.K;
  if (p.mode == M_AV) kend = min(p.K, m0 + 128);
  int nk = kend >> 4;

  uint32_t* Asm = dynsmem;
  uint32_t* Bsm = dynsmem + STAGES * STW;

  int tid = threadIdx.x;
  int lane = tid & 31, wid = tid >> 5;
  int warp_m = wid & 1, warp_n = wid >> 1;
  int gid = lane >> 2, tig = lane & 3;

  uint32_t as_base = (uint32_t)__cvta_generic_to_shared(Asm);
  uint32_t bs_base = (uint32_t)__cvta_generic_to_shared(Bsm);
  int lm_row = (lane & 15);
  int lm_col = (lane >> 4) << 2;

  float acc[4][4][4];
#pragma unroll
  for (int a = 0; a < 4; a++)
#pragma unroll
    for (int b = 0; b < 4; b++)
#pragma unroll
      for (int c = 0; c < 4; c++) acc[a][b][c] = 0.f;

  int a_row0 = tid >> 2, a_kq = (tid & 3) * 4;
  const float* a_src0;
  const float* a_src1;
  {
    int gm0 = m0 + a_row0, gm1 = m0 + a_row0 + 64;
    a_src0 = (gm0 < Meff) ? Ab + (size_t)gm0 * p.lda : Ab;
    a_src1 = (gm1 < Meff) ? Ab + (size_t)gm1 * p.lda : Ab;
  }
  bool a_v0 = (m0 + a_row0) < Meff;
  bool a_v1 = (m0 + a_row0 + 64) < Meff;

  auto issue = [&](int it, int st) {
    if (it < nk) {
      int k0 = it << 4;
      cp_async16(as_base + (uint32_t)(st * STW + a_row0 * APAD + a_kq) * 4u,
                 a_src0 + k0 + a_kq, a_v0);
      cp_async16(
          as_base + (uint32_t)(st * STW + (a_row0 + 64) * APAD + a_kq) * 4u,
          a_src1 + k0 + a_kq, a_v1);
      if (p.transB) {
        int n = tid >> 2, kq = (tid & 3) * 4;
        cp_async16(bs_base + (uint32_t)(st * STW + n * APAD + kq) * 4u,
                   Bb + (size_t)(n0 + n) * p.ldb + k0 + kq, true);
        cp_async16(bs_base + (uint32_t)(st * STW + (n + 64) * APAD + kq) * 4u,
                   Bb + (size_t)(n0 + n + 64) * p.ldb + k0 + kq, true);
      } else {
        int kk = tid >> 5, nq = (tid & 31) * 4;
        cp_async16(bs_base + (uint32_t)(st * STW + kk * BPAD + nq) * 4u,
                   Bb + (size_t)(k0 + kk) * p.ldb + n0 + nq, true);
        cp_async16(bs_base + (uint32_t)(st * STW + (kk + 8) * BPAD + nq) * 4u,
                   Bb + (size_t)(k0 + kk + 8) * p.ldb + n0 + nq, true);
      }
    }
    cp_commit();
  };

  issue(0, 0);
  issue(1, 1);
  issue(2, 2);

  int cur = 0;
  for (int it = 0; it < nk; it++) {
    cp_wait<STAGES - 2>();
    __syncthreads();
    issue(it + 3, (cur + 3) & (STAGES - 1));

    const uint32_t* Bsp = Bsm + cur * STW;
#pragma unroll
    for (int ks = 0; ks < 16; ks += 8) {
      uint32_t afr[4][4];
#pragma unroll
      for (int mt = 0; mt < 4; mt++) {
        int row = warp_m * 64 + mt * 16 + lm_row;
        uint32_t saddr =
            as_base + (uint32_t)(cur * STW + row * APAD + ks + lm_col) * 4u;
        ldsm4(afr[mt], saddr);
      }
      uint32_t bfr[4][2];
      if (p.transB) {
#pragma unroll
        for (int nt = 0; nt < 4; nt++) {
          int ncol = warp_n * 32 + nt * 8 + gid;
          bfr[nt][0] = Bsp[ncol * APAD + ks + tig];
          bfr[nt][1] = Bsp[ncol * APAD + ks + tig + 4];
        }
      } else {
#pragma unroll
        for (int nt = 0; nt < 4; nt++) {
          int ncol = warp_n * 32 + nt * 8 + gid;
          bfr[nt][0] = Bsp[(ks + tig) * BPAD + ncol];
          bfr[nt][1] = Bsp[(ks + tig + 4) * BPAD + ncol];
        }
      }
#pragma unroll
      for (int mt = 0; mt < 4; mt++)
#pragma unroll
        for (int nt = 0; nt < 4; nt++) mma_tf32(acc[mt][nt], afr[mt], bfr[nt]);
    }
    cur = (cur + 1) & (STAGES - 1);
  }

#pragma unroll
  for (int mt = 0; mt < 4; mt++) {
#pragma unroll
    for (int nt = 0; nt < 4; nt++) {
#pragma unroll
      for (int ee = 0; ee < 4; ee++) {
        int gm = m0 + warp_m * 64 + mt * 16 + gid + (ee >= 2 ? 8 : 0);
        int gn = n0 + warp_n * 32 + nt * 8 + tig * 2 + (ee & 1);
        if (gm >= Meff) continue;
        float v = acc[mt][nt][ee];
        if (p.mode == M_QKV)
          v += p.bias[gn];
        else if (p.mode == M_WO)
          v += p.resid[(size_t)gm * p.ldc + gn];
        else if (p.mode == M_SCORES) {
          if (gn > gm) continue;
          v *= SCALE;
        }
        Cb[(size_t)gm * p.ldc + gn] = v;
      }
    }
  }
}

// ---------------------------------------------------------------------------
// fp16 MoE GEMM. Block 128(M) x 128(B-tile cols), warps 2x4, warp tile 64x32.
// A: packed fp16 in global (xt16 gathered / act16 dense), cp.async -> smem
//    [m][40 halves], fragments via ldmatrix.x4.
// B: fp32 weights, LDG+convert in-kernel into packed k-pair words [kp][136].
// mode 0 (GU): B tile interleaves gate/up in 8-col groups; epilogue fuses
//              SiLU in-register -> act16.
// mode 1 (DN): epilogue scatter-atomicAdd into comb[token].
// ---------------------------------------------------------------------------
struct F16P {
  int mode;  // 0 = GU, 1 = DN
  const __half* A;
  const float* Bm;
  __half* Ch;          // GU output (act16)
  float* Cf;           // DN output (comb)
  const int* gidx;     // GU: gather rows; DN: token map
  const int* cnt;
  const float* wslot;  // DN
  int lda;             // halves
  int ldb;             // fp32 words
  int K;
};

constexpr int HAPAD = 40;                // halves per A row slot
constexpr int F16_ASTW = 128 * HAPAD;    // halves per A stage (5120)
constexpr int F16_BSTW = 16 * 136;       // words per B stage (2176)

__global__ __launch_bounds__(256, 2) void gemm_f16(F16P p) {
  int z = blockIdx.z;
  int Meff = min(p.cnt[z], CAP);
  int m0 = blockIdx.y * 128;
  if (m0 >= Meff) return;

  const __half* Ab;
  const float* Bb;
  const int* gidx = nullptr;
  const int* tokz = nullptr;
  const float* wz = nullptr;
  int n0g = 0, n0 = 0;
  if (p.mode == 0) {
    Ab = p.A;  // xt16, gathered
    gidx = p.gidx + z * CAP;
    Bb = p.Bm + (size_t)z * H * (2 * FI);
    n0g = blockIdx.x * 64;
  } else {
    Ab = p.A + (size_t)z * CAP * FI;  // act16, dense
    Bb = p.Bm + (size_t)z * FI * H;
    tokz = p.gidx + z * CAP;
    wz = p.wslot + z * CAP;
    n0 = blockIdx.x * 128;
  }

  __shared__ __half Ash[2][F16_ASTW];
  __shared__ uint32_t Bsh[2][F16_BSTW];

  int tid = threadIdx.x;
  int lane = tid & 31, wid = tid >> 5;
  int warp_m = wid & 1, warp_n = wid >> 1;
  int gid = lane >> 2, tig = lane & 3;

  uint32_t as_base = (uint32_t)__cvta_generic_to_shared(&Ash[0][0]);

  int nk = p.K >> 5;  // K-tile = 32

  float acc[4][4][4];
#pragma unroll
  for (int a = 0; a < 4; a++)
#pragma unroll
    for (int b = 0; b < 4; b++)
#pragma unroll
      for (int c = 0; c < 4; c++) acc[a][b][c] = 0.f;

  int a_row0 = tid >> 2, a_kq = (tid & 3) * 8;
  const __half* a_src0;
  const __half* a_src1;
  {
    int gm0 = m0 + a_row0, gm1 = m0 + a_row0 + 64;
    a_src0 = (gm0 < Meff)
                 ? (gidx ? Ab + (size_t)gidx[gm0] * p.lda
                         : Ab + (size_t)gm0 * p.lda)
                 : Ab;
    a_src1 = (gm1 < Meff)
                 ? (gidx ? Ab + (size_t)gidx[gm1] * p.lda
                         : Ab + (size_t)gm1 * p.lda)
                 : Ab;
  }
  bool a_v0 = (m0 + a_row0) < Meff;
  bool a_v1 = (m0 + a_row0 + 64) < Meff;

  auto issueA = [&](int it, int st) {
    if (it < nk) {
      int k0h = it << 5;
      cp_async16(
          as_base + (uint32_t)(st * F16_ASTW + a_row0 * HAPAD + a_kq) * 2u,
          a_src0 + k0h + a_kq, a_v0);
      cp_async16(
          as_base +
              (uint32_t)(st * F16_ASTW + (a_row0 + 64) * HAPAD + a_kq) * 2u,
          a_src1 + k0h + a_kq, a_v1);
    }
    cp_commit();
  };

  int b_kp0 = tid >> 5, b_nq0 = (tid & 31) * 4;
  auto bcol = [&](int n) -> int {
    if (p.mode == 0) {
      int grp = n >> 4;
      int isup = (n >> 3) & 1;
      int cc = grp * 8 + (n & 7);
      return (isup ? FI : 0) + n0g + cc;
    }
    return n0 + n;
  };
  int b_c0 = bcol(b_nq0);
  int b_c1 = bcol((((tid + 256) & 31) * 4));
  int b_kp1 = (tid + 256) >> 5;

  uint32_t bstage[8];
  auto loadB = [&](int it) {
    if (it < nk) {
      int k0 = it << 5;
      const float* r0 = Bb + (size_t)(k0 + 2 * b_kp0) * p.ldb + b_c0;
      float4 f0 = *(const float4*)r0;
      float4 f1 = *(const float4*)(r0 + p.ldb);
      bstage[0] = h2u(__floats2half2_rn(f0.x, f1.x));
      bstage[1] = h2u(__floats2half2_rn(f0.y, f1.y));
      bstage[2] = h2u(__floats2half2_rn(f0.z, f1.z));
      bstage[3] = h2u(__floats2half2_rn(f0.w, f1.w));
      const float* r2 = Bb + (size_t)(k0 + 2 * b_kp1) * p.ldb + b_c1;
      float4 f2 = *(const float4*)r2;
      float4 f3 = *(const float4*)(r2 + p.ldb);
      bstage[4] = h2u(__floats2half2_rn(f2.x, f3.x));
      bstage[5] = h2u(__floats2half2_rn(f2.y, f3.y));
      bstage[6] = h2u(__floats2half2_rn(f2.z, f3.z));
      bstage[7] = h2u(__floats2half2_rn(f2.w, f3.w));
    }
  };
  auto storeB = [&](int it, int st) {
    if (it < nk) {
      uint32_t* d0 = &Bsh[st][b_kp0 * 136 + b_nq0];
      d0[0] = bstage[0];
      d0[1] = bstage[1];
      d0[2] = bstage[2];
      d0[3] = bstage[3];
      uint32_t* d1 = &Bsh[st][b_kp1 * 136 + (((tid + 256) & 31) * 4)];
      d1[0] = bstage[4];
      d1[1] = bstage[5];
      d1[2] = bstage[6];
      d1[3] = bstage[7];
    }
  };

  // prologue: fill stage 0
  issueA(0, 0);
  loadB(0);
  storeB(0, 0);
  cp_wait<0>();
  __syncthreads();

  int cur = 0;
  for (int it = 0; it < nk; it++) {
    issueA(it + 1, cur ^ 1);
    loadB(it + 1);

    const uint32_t* Bsp = &Bsh[cur][0];
#pragma unroll
    for (int ks = 0; ks < 2; ks++) {
      uint32_t afr[4][4];
#pragma unroll
      for (int mt = 0; mt < 4; mt++) {
        int row = warp_m * 64 + mt * 16 + (lane & 15);
        uint32_t saddr =
            as_base + (uint32_t)(cur * F16_ASTW + row * HAPAD + ks * 16 +
                                 ((lane >> 4) << 3)) *
                          2u;
        ldsm4(afr[mt], saddr);
      }
      uint32_t bfr[4][2];
      int kpb = ks * 8;
#pragma unroll
      for (int nt = 0; nt < 4; nt++) {
        int ncol = warp_n * 32 + nt * 8 + gid;
        bfr[nt][0] = Bsp[(kpb + tig) * 136 + ncol];
        bfr[nt][1] = Bsp[(kpb + 4 + tig) * 136 + ncol];
      }
#pragma unroll
      for (int mt = 0; mt < 4; mt++)
#pragma unroll
        for (int nt = 0; nt < 4; nt++) mma_f16(acc[mt][nt], afr[mt], bfr[nt]);
    }

    storeB(it + 1, cur ^ 1);
    cp_wait<0>();
    __syncthreads();
    cur ^= 1;
  }

  if (p.mode == 0) {
#pragma unroll
    for (int mt = 0; mt < 4; mt++) {
#pragma unroll
      for (int q = 0; q < 2; q++) {
#pragma unroll
        for (int half_e = 0; half_e < 2; half_e++) {
          int gm = m0 + warp_m * 64 + mt * 16 + gid + half_e * 8;
          if (gm >= Meff) continue;
          float g0 = acc[mt][2 * q][half_e * 2 + 0];
          float g1 = acc[mt][2 * q][half_e * 2 + 1];
          float u0 = acc[mt][2 * q + 1][half_e * 2 + 0];
          float u1 = acc[mt][2 * q + 1][half_e * 2 + 1];
          float a0 = (g0 / (1.f + expf(-g0))) * u0;
          float a1 = (g1 / (1.f + expf(-g1))) * u1;
          int cc = n0g + (2 * warp_n + q) * 8 + tig * 2;
          __half2 h = __floats2half2_rn(a0, a1);
          *(__half2*)&p.Ch[(size_t)z * CAP * FI + (size_t)gm * FI + cc] = h;
        }
      }
    }
  } else {
#pragma unroll
    for (int mt = 0; mt < 4; mt++) {
#pragma unroll
      for (int nt = 0; nt < 4; nt++) {
#pragma unroll
        for (int ee = 0; ee < 4; ee++) {
          int gm = m0 + warp_m * 64 + mt * 16 + gid + (ee >= 2 ? 8 : 0);
          if (gm >= Meff) continue;
          int gn = n0 + warp_n * 32 + nt * 8 + tig * 2 + (ee & 1);
          int t = tokz[gm];
          float w = wz[gm];
          atomicAdd(&p.Cf[(size_t)t * H + gn], acc[mt][nt][ee] * w);
        }
      }
    }
  }
}

// ---------------------------------------------------------------------------
// fp32 SIMT GEMM (tiny gate GEMM -> exact routing inputs)
// ---------------------------------------------------------------------------
__global__ __launch_bounds__(256) void gemm_kernel(GemmP p) {
  const float* Ab = p.A;
  const float* Bb = p.Bm;
  float* Cb = p.C;
  int Meff = p.M;

  int m0 = blockIdx.y * 64, n0 = blockIdx.x * 64;
  if (m0 >= Meff) return;

  __shared__ float As[16][68];
  __shared__ float Bs[16][68];
  int tid = threadIdx.x, tx = tid & 15, ty = tid >> 4;
  float acc[4][4] = {};

  for (int k0 = 0; k0 < p.K; k0 += 16) {
#pragma unroll
    for (int l = 0; l < 4; l++) {
      int i = tid + l * 256;
      int row = i >> 4, col = i & 15;
      int gm = m0 + row;
      float v = 0.f;
      if (gm < Meff) v = Ab[(size_t)gm * p.lda + k0 + col];
      As[col][row] = v;
    }
#pragma unroll
    for (int l = 0; l < 4; l++) {
      int i = tid + l * 256;
      if (p.transB) {
        int col = i >> 4, kk = i & 15;
        Bs[kk][col] = Bb[(size_t)(n0 + col) * p.ldb + (k0 + kk)];
      } else {
        int kk = i >> 6, col = i & 63;
        Bs[kk][col] = Bb[(size_t)(k0 + kk) * p.ldb + (n0 + col)];
      }
    }
    __syncthreads();
#pragma unroll
    for (int kk = 0; kk < 16; kk++) {
      float4 a4 = *(const float4*)(&As[kk][ty * 4]);
      float4 b4 = *(const float4*)(&Bs[kk][tx * 4]);
      float av[4] = {a4.x, a4.y, a4.z, a4.w};
      float bv[4] = {b4.x, b4.y, b4.z, b4.w};
#pragma unroll
      for (int i = 0; i < 4; i++)
#pragma unroll
        for (int j = 0; j < 4; j++) acc[i][j] += av[i] * bv[j];
    }
    __syncthreads();
  }

#pragma unroll
  for (int i = 0; i < 4; i++) {
    int gm = m0 + ty * 4 + i;
    if (gm >= Meff) continue;
#pragma unroll
    for (int j = 0; j < 4; j++) {
      int gn = n0 + tx * 4 + j;
      Cb[(size_t)gm * p.ldc + gn] = acc[i][j];
    }
  }
}

// ---------------------------------------------------------------------------
// Row softmax, causal-aware.
// ---------------------------------------------------------------------------
__global__ void softmax_kernel(float* __restrict__ sc) {
  size_t row = blockIdx.x;
  int q = (int)(row & (S - 1));
  int len = q + 1;
  int fill_end = ((q >> 7) + 1) << 7;
  float* p = sc + row * (size_t)S;
  __shared__ float red[8];
  float mx = -INFINITY;
  for (int i = threadIdx.x; i < len; i += 256) mx = fmaxf(mx, p[i]);
  for (int o = 16; o; o >>= 1) mx = fmaxf(mx, __shfl_xor_sync(~0u, mx, o));
  if ((threadIdx.x & 31) == 0) red[threadIdx.x >> 5] = mx;
  __syncthreads();
  if (threadIdx.x == 0) {
    float m = red[0];
    for (int i = 1; i < 8; i++) m = fmaxf(m, red[i]);
    red[0] = m;
  }
  __syncthreads();
  mx = red[0];
  __syncthreads();
  float sum = 0.f;
  for (int i = threadIdx.x; i < len; i += 256) {
    float e = expf(p[i] - mx);
    p[i] = e;
    sum += e;
  }
  for (int o = 16; o; o >>= 1) sum += __shfl_xor_sync(~0u, sum, o);
  if ((threadIdx.x & 31) == 0) red[threadIdx.x >> 5] = sum;
  __syncthreads();
  if (threadIdx.x == 0) {
    float t = 0.f;
    for (int i = 0; i < 8; i++) t += red[i];
    red[0] = t;
  }
  __syncthreads();
  float inv = 1.f / red[0];
  for (int i = threadIdx.x; i < len; i += 256) p[i] *= inv;
  for (int i = len + threadIdx.x; i < fill_end; i += 256) p[i] = 0.f;
}

// ---------------------------------------------------------------------------
// Routing
// ---------------------------------------------------------------------------
__global__ void route_kernel(const float* __restrict__ logits,
                             const float* __restrict__ gate_b,
                             int* __restrict__ topi, float* __restrict__ fw) {
  int t = blockIdx.x * blockDim.x + threadIdx.x;
  if (t >= T) return;
  float corr[E];
  const float* lg = logits + (size_t)t * E;
  for (int e = 0; e < E; e++) {
    float s = 1.f / (1.f + expf(-lg[e]));
    corr[e] = s + gate_b[e];
  }
  float grp[NG];
  for (int g = 0; g < NG; g++) {
    float m1 = -INFINITY, m2 = -INFINITY;
    for (int i = 0; i < E / NG; i++) {
      float v = corr[g * (E / NG) + i];
      if (v > m1) {
        m2 = m1;
        m1 = v;
      } else if (v > m2) {
        m2 = v;
      }
    }
    grp[g] = m1 + m2;
  }
  unsigned gsel = 0;
  for (int it = 0; it < TG; it++) {
    float best = -INFINITY;
    int bi = 0;
    for (int g = 0; g < NG; g++)
      if (!((gsel >> g) & 1u) && grp[g] > best) {
        best = grp[g];
        bi = g;
      }
    gsel |= 1u << bi;
  }
  unsigned long long esel = 0ull;
  int sel[TK];
  float ws[TK];
  float wsum = 0.f;
  for (int it = 0; it < TK; it++) {
    float best = -INFINITY;
    int bi = 0;
    for (int e = 0; e < E; e++) {
      if (!((gsel >> (e >> 3)) & 1u)) continue;
      if ((esel >> e) & 1ull) continue;
      if (corr[e] > best) {
        best = corr[e];
        bi = e;
      }
    }
    esel |= 1ull << bi;
    sel[it] = bi;
    float s = corr[bi] - gate_b[bi];
    ws[it] = s;
    wsum += s;
  }
  float inv = 1.f / wsum;
  for (int j = 0; j < TK; j++) {
    topi[t * TK + j] = sel[j];
    fw[t * TK + j] = ws[j] * inv;
  }
}

__global__ void zero_cnt_kernel(int* __restrict__ cnt) {
  if (threadIdx.x < E) cnt[threadIdx.x] = 0;
}

__global__ void assign_kernel(const int* __restrict__ topi,
                              const float* __restrict__ fw,
                              int* __restrict__ cnt, int* __restrict__ tok,
                              float* __restrict__ wslot) {
  int i = blockIdx.x * blockDim.x + threadIdx.x;
  if (i >= T * TK) return;
  int e = topi[i];
  int p = atomicAdd(&cnt[e], 1);
  if (p < CAP) {
    tok[e * CAP + p] = i / TK;
    wslot[e * CAP + p] = fw[i];
  }
}

// ---------------------------------------------------------------------------
// shared expert SiLU
// ---------------------------------------------------------------------------
__global__ void shared_act_kernel(const float* __restrict__ sgu,
                                  float* __restrict__ act) {
  size_t idx = (size_t)blockIdx.x * 256 + threadIdx.x;
  if (idx >= (size_t)T * FSH) return;
  int t = (int)(idx / FSH), f = (int)(idx % FSH);
  const float* gr = sgu + (size_t)t * (2 * FSH);
  float g = gr[f], u = gr[FSH + f];
  act[(size_t)t * FSH + f] = (g / (1.f + expf(-g))) * u;
}

// ---------------------------------------------------------------------------
// Final: out = h2 + comb
// ---------------------------------------------------------------------------
__global__ void final_kernel(const float* __restrict__ h2,
                             const float* __restrict__ comb,
                             float* __restrict__ out) {
  size_t i = (size_t)blockIdx.x * 256 + threadIdx.x;
  if (i < (size_t)T * H) out[i] = h2[i] + comb[i];
}

// ---------------------------------------------------------------------------
// Host launcher
// ---------------------------------------------------------------------------
extern "C" void kernel_launch(void* const* d_in, const int* in_sizes, int n_in,
                              void* d_out, int out_size) {
  const float* x = (const float*)d_in[0];
  const int* positions = (const int*)d_in[1];
  const float* ln1_w = (const float*)d_in[2];
  const float* ln2_w = (const float*)d_in[3];
  const float* wqkv = (const float*)d_in[4];
  const float* bqkv = (const float*)d_in[5];
  const float* qn_w = (const float*)d_in[6];
  const float* kn_w = (const float*)d_in[7];
  const float* wo = (const float*)d_in[8];
  const float* gate_w = (const float*)d_in[9];
  const float* gate_b = (const float*)d_in[10];
  const float* w_gu = (const float*)d_in[11];
  const float* w_dn = (const float*)d_in[12];
  const float* sw_gu = (const float*)d_in[13];
  const float* sw_dn = (const float*)d_in[14];
  float* out = (float*)d_out;

  static bool attr_set = false;
  if (!attr_set) {
    cudaFuncSetAttribute(gemm_tc, cudaFuncAttributeMaxDynamicSharedMemorySize,
                         GEMM_DSMEM);
    attr_set = true;
  }

  float* scr = nullptr;
  cudaGetSymbolAddress((void**)&scr, g_scratch);
  int* topi = nullptr;
  cudaGetSymbolAddress((void**)&topi, g_topi);
  int* cnt = nullptr;
  cudaGetSymbolAddress((void**)&cnt, g_cnt);
  int* tok = nullptr;
  cudaGetSymbolAddress((void**)&tok, g_tok);
  float* wslot = nullptr;
  cudaGetSymbolAddress((void**)&wslot, g_wslot);
  __half* xt16 = nullptr;
  cudaGetSymbolAddress((void**)&xt16, g_xt16);
  __half* act16 = nullptr;
  cudaGetSymbolAddress((void**)&act16, g_act16);

  float* bh = scr + OFF_H;
  float* bqkvb = scr + OFF_QKV;
  float* bq = scr + OFF_Q;
  float* bk = scr + OFF_K;
  float* bsc = scr + OFF_SC;
  float* baout = scr + OFF_AOUT;
  float* bh2 = scr + OFF_H2;
  float* bxt = scr + OFF_XT;
  float* blog = scr + OFF_LOG;
  float* bfw = scr + OFF_FW;
  float* bsgu = scr + OFF_SGU;
  float* bshact = scr + OFF_SHACT;
  float* bcomb = scr + OFF_COMB;

  // 1. rmsnorm1
  rmsnorm_kernel<<<T, 256>>>(x, ln1_w, bh, nullptr, H);

  // 2. qkv
  {
    GemmP p{};
    p.mode = M_QKV;
    p.A = bh; p.Bm = wqkv; p.C = bqkvb; p.bias = bqkv;
    p.M = T; p.N = QKVW; p.K = H;
    p.lda = H; p.ldb = H; p.ldc = QKVW; p.transB = 1;
    gemm_tc<<<dim3(QKVW / 128, T / 128, 1), 256, GEMM_DSMEM>>>(p);
  }

  // 3. q/k rmsnorm + rope
  qknorm_rope_kernel<<<dim3(T, NH + NKV), 128>>>(bqkvb, positions, qn_w, kn_w,
                                                 bq, bk);

  // 4. scores
  {
    GemmP p{};
    p.mode = M_SCORES;
    p.A = bq; p.Bm = bk; p.C = bsc;
    p.M = S; p.N = S; p.K = D;
    p.lda = NH * D; p.ldb = NKV * D; p.ldc = S; p.transB = 1;
    gemm_tc<<<dim3(S / 128, S / 128, B * NH), 256, GEMM_DSMEM>>>(p);
  }

  // 5. softmax
  softmax_kernel<<<B * NH * S, 256>>>(bsc);

  // 6. attn @ v
  {
    GemmP p{};
    p.mode = M_AV;
    p.A = bsc; p.Bm = bqkvb; p.C = baout;
    p.M = S; p.N = D; p.K = S;
    p.lda = S; p.ldb = QKVW; p.ldc = NH * D; p.transB = 0;
    gemm_tc<<<dim3(D / 128, S / 128, B * NH), 256, GEMM_DSMEM>>>(p);
  }

  // 7. h2 = x + aout @ wo^T
  {
    GemmP p{};
    p.mode = M_WO;
    p.A = baout; p.Bm = wo; p.C = bh2; p.resid = x;
    p.M = T; p.N = H; p.K = NH * D;
    p.lda = NH * D; p.ldb = NH * D; p.ldc = H; p.transB = 1;
    gemm_tc<<<dim3(H / 128, T / 128, 1), 256, GEMM_DSMEM>>>(p);
  }

  // 8. rmsnorm2 (fp32 + fp16 copies)
  rmsnorm_kernel<<<T, 256>>>(bh2, ln2_w, bxt, xt16, H);

  // 9. gate logits (exact fp32)
  {
    GemmP p{};
    p.mode = M_GATE;
    p.A = bxt; p.Bm = gate_w; p.C = blog;
    p.M = T; p.N = E; p.K = H;
    p.lda = H; p.ldb = H; p.ldc = E; p.transB = 1;
    gemm_kernel<<<dim3(1, T / 64, 1), 256>>>(p);
  }

  // 10. routing
  route_kernel<<<T / 256, 256>>>(blog, gate_b, topi, bfw);
  zero_cnt_kernel<<<1, 64>>>(cnt);
  assign_kernel<<<(T * TK) / 256, 256>>>(topi, bfw, cnt, tok, wslot);

  // 11. shared expert -> bcomb (precedes MoE scatter)
  {
    GemmP p{};
    p.mode = M_SGU;
    p.A = bxt; p.Bm = sw_gu; p.C = bsgu;
    p.M = T; p.N = 2 * FSH; p.K = H;
    p.lda = H; p.ldb = 2 * FSH; p.ldc = 2 * FSH; p.transB = 0;
    gemm_tc<<<dim3((2 * FSH) / 128, T / 128, 1), 256, GEMM_DSMEM>>>(p);
  }
  shared_act_kernel<<<(int)(((size_t)T * FSH + 255) / 256), 256>>>(bsgu,
                                                                   bshact);
  {
    GemmP p{};
    p.mode = M_SDN;
    p.A = bshact; p.Bm = sw_dn; p.C = bcomb;
    p.M = T; p.N = H; p.K = FSH;
    p.lda = FSH; p.ldb = H; p.ldc = H; p.transB = 0;
    gemm_tc<<<dim3(H / 128, T / 128, 1), 256, GEMM_DSMEM>>>(p);
  }

  // 12. MoE up-gate (fp16) fused SiLU -> act16
  {
    F16P p{};
    p.mode = 0;
    p.A = xt16; p.Bm = w_gu; p.Ch = act16;
    p.gidx = tok; p.cnt = cnt;
    p.lda = H; p.ldb = 2 * FI; p.K = H;
    gemm_f16<<<dim3(FI / 64, CAP / 128, E), 256>>>(p);
  }

  // 13. MoE down (fp16), scatter-accumulate into bcomb
  {
    F16P p{};
    p.mode = 1;
    p.A = act16; p.Bm = w_dn; p.Cf = bcomb;
    p.gidx = tok; p.cnt = cnt; p.wslot = wslot;
    p.lda = FI; p.ldb = H; p.K = FI;
    gemm_f16<<<dim3(H / 128, CAP / 128, E), 256>>>(p);
  }

  // 14. out = h2 + comb
  final_kernel<<<(int)(((size_t)T * H + 255) / 256), 256>>>(bh2, bcomb, out);
}

// round 9
// speedup vs baseline: 1.2037x; 1.0256x over previous
#include <cuda_runtime.h>
#include <cuda_fp16.h>
#include <math.h>
#include <stdint.h>

// ---------------------------------------------------------------------------
// Problem constants
// ---------------------------------------------------------------------------
namespace cfg {
constexpr int B = 2, S = 1024, H = 1024;
constexpr int NH = 8, NKV = 2, D = 128, ROT = 64;
constexpr int E = 64, TK = 8, NG = 8, TG = 4;
constexpr int FI = 512, FSH = 512, CAP = 512;
constexpr int T = B * S;                  // 2048 tokens
constexpr int QKVW = (NH + 2 * NKV) * D;  // 1536
constexpr float EPS = 1e-5f;
constexpr float SCALE = 0.08838834764831843f;  // 128^-0.5
constexpr float THETA = 10000.0f;
}  // namespace cfg

using namespace cfg;

// ---------------------------------------------------------------------------
// Static device scratch (no allocations allowed)
// ---------------------------------------------------------------------------
constexpr size_t N_H      = (size_t)T * H;
constexpr size_t N_QKV    = (size_t)T * QKVW;
constexpr size_t N_Q      = (size_t)T * NH * D;
constexpr size_t N_K      = (size_t)T * NKV * D;
constexpr size_t N_SC     = (size_t)B * NH * S * S;
constexpr size_t N_AOUT   = (size_t)T * NH * D;
constexpr size_t N_H2     = (size_t)T * H;
constexpr size_t N_XT     = (size_t)T * H;
constexpr size_t N_LOG    = (size_t)T * E;
constexpr size_t N_FW     = (size_t)T * TK;
constexpr size_t N_COMB   = (size_t)T * H;

constexpr size_t OFF_H      = 0;
constexpr size_t OFF_QKV    = OFF_H + N_H;
constexpr size_t OFF_Q      = OFF_QKV + N_QKV;
constexpr size_t OFF_K      = OFF_Q + N_Q;
constexpr size_t OFF_SC     = OFF_K + N_K;
constexpr size_t OFF_AOUT   = OFF_SC + N_SC;
constexpr size_t OFF_H2     = OFF_AOUT + N_AOUT;
constexpr size_t OFF_XT     = OFF_H2 + N_H2;
constexpr size_t OFF_LOG    = OFF_XT + N_XT;
constexpr size_t OFF_FW     = OFF_LOG + N_LOG;
constexpr size_t OFF_COMB   = OFF_FW + N_FW;
constexpr size_t SCRATCH_F  = OFF_COMB + N_COMB;

__device__ float g_scratch[SCRATCH_F];
__device__ __half g_xt16[(size_t)T * H];
__device__ __half g_bh16[(size_t)T * H];
__device__ __half g_aout16[(size_t)T * NH * D];
__device__ __half g_shact16[(size_t)T * FSH];
__device__ __half g_act16[(size_t)E * CAP * FI];

__device__ int g_topi[T * TK];
__device__ int g_cnt[E];
__device__ int g_tok[E * CAP];
__device__ float g_wslot[E * CAP];

// ---------------------------------------------------------------------------
// mma / cp.async helpers
// ---------------------------------------------------------------------------
__device__ __forceinline__ uint32_t h2u(__half2 h) {
  return *reinterpret_cast<uint32_t*>(&h);
}

__device__ __forceinline__ void mma_tf32(float c[4], const uint32_t a[4],
                                         const uint32_t b[2]) {
  asm volatile(
      "mma.sync.aligned.m16n8k8.row.col.f32.tf32.tf32.f32 "
      "{%0,%1,%2,%3}, {%4,%5,%6,%7}, {%8,%9}, {%0,%1,%2,%3};\n"
      : "+f"(c[0]), "+f"(c[1]), "+f"(c[2]), "+f"(c[3])
      : "r"(a[0]), "r"(a[1]), "r"(a[2]), "r"(a[3]), "r"(b[0]), "r"(b[1]));
}

__device__ __forceinline__ void mma_f16(float c[4], const uint32_t a[4],
                                        const uint32_t b[2]) {
  asm volatile(
      "mma.sync.aligned.m16n8k16.row.col.f32.f16.f16.f32 "
      "{%0,%1,%2,%3}, {%4,%5,%6,%7}, {%8,%9}, {%0,%1,%2,%3};\n"
      : "+f"(c[0]), "+f"(c[1]), "+f"(c[2]), "+f"(c[3])
      : "r"(a[0]), "r"(a[1]), "r"(a[2]), "r"(a[3]), "r"(b[0]), "r"(b[1]));
}

__device__ __forceinline__ void ldsm4(uint32_t r[4], uint32_t saddr) {
  asm volatile(
      "ldmatrix.sync.aligned.m8n8.x4.shared.b16 {%0,%1,%2,%3}, [%4];"
      : "=r"(r[0]), "=r"(r[1]), "=r"(r[2]), "=r"(r[3])
      : "r"(saddr));
}

__device__ __forceinline__ void cp_async16(uint32_t dst, const void* src,
                                           bool pred) {
  int sz = pred ? 16 : 0;
  asm volatile("cp.async.cg.shared.global [%0], [%1], 16, %2;\n" ::"r"(dst),
               "l"(src), "r"(sz));
}
__device__ __forceinline__ void cp_commit() {
  asm volatile("cp.async.commit_group;\n");
}
template <int N>
__device__ __forceinline__ void cp_wait() {
  asm volatile("cp.async.wait_group %0;\n" ::"n"(N));
}

// ---------------------------------------------------------------------------
// RMSNorm (optional packed fp16 second output)
// ---------------------------------------------------------------------------
__global__ void rmsnorm_kernel(const float* __restrict__ in,
                               const float* __restrict__ w,
                               float* __restrict__ out,
                               __half* __restrict__ out16, int dim) {
  int t = blockIdx.x;
  const float* r = in + (size_t)t * dim;
  float s = 0.f;
  for (int i = threadIdx.x; i < dim; i += 256) {
    float v = r[i];
    s += v * v;
  }
  for (int o = 16; o; o >>= 1) s += __shfl_xor_sync(~0u, s, o);
  __shared__ float red[8];
  if ((threadIdx.x & 31) == 0) red[threadIdx.x >> 5] = s;
  __syncthreads();
  if (threadIdx.x == 0) {
    float tt = 0.f;
    for (int i = 0; i < 8; i++) tt += red[i];
    red[0] = tt;
  }
  __syncthreads();
  float inv = rsqrtf(red[0] / (float)dim + EPS);
  for (int i = threadIdx.x * 2; i < dim; i += 512) {
    float v0 = r[i] * inv * w[i];
    float v1 = r[i + 1] * inv * w[i + 1];
    out[(size_t)t * dim + i] = v0;
    out[(size_t)t * dim + i + 1] = v1;
    if (out16) {
      __half2 h = __floats2half2_rn(v0, v1);
      *(__half2*)&out16[(size_t)t * dim + i] = h;
    }
  }
}

// ---------------------------------------------------------------------------
// Per-head Q/K RMSNorm + RoPE
// ---------------------------------------------------------------------------
__global__ void qknorm_rope_kernel(const float* __restrict__ qkv,
                                   const int* __restrict__ positions,
                                   const float* __restrict__ qn,
                                   const float* __restrict__ kn,
                                   float* __restrict__ qout,
                                   float* __restrict__ kout) {
  int t = blockIdx.x, hh = blockIdx.y, d = threadIdx.x;
  const float* src;
  const float* w;
  float* dst;
  if (hh < NH) {
    src = qkv + (size_t)t * QKVW + hh * D;
    w = qn;
    dst = qout + ((size_t)t * NH + hh) * D;
  } else {
    int kv = hh - NH;
    src = qkv + (size_t)t * QKVW + NH * D + kv * D;
    w = kn;
    dst = kout + ((size_t)t * NKV + kv) * D;
  }
  float v = src[d];
  float s = v * v;
  for (int o = 16; o; o >>= 1) s += __shfl_xor_sync(~0u, s, o);
  __shared__ float red[4];
  if ((d & 31) == 0) red[d >> 5] = s;
  __syncthreads();
  float tot = red[0] + red[1] + red[2] + red[3];
  float nv = v * rsqrtf(tot / (float)D + EPS) * w[d];
  __shared__ float sh[128];
  sh[d] = nv;
  __syncthreads();
  int sidx = t & (S - 1);
  float pos = (float)positions[sidx];
  float res;
  if (d < ROT / 2) {
    float ang = pos * powf(THETA, -(float)d / (float)(ROT / 2));
    res = sh[d] * cosf(ang) - sh[d + ROT / 2] * sinf(ang);
  } else if (d < ROT) {
    int i2 = d - ROT / 2;
    float ang = pos * powf(THETA, -(float)i2 / (float)(ROT / 2));
    res = sh[d] * cosf(ang) + sh[d - ROT / 2] * sinf(ang);
  } else {
    res = nv;
  }
  dst[d] = res;
}

// ---------------------------------------------------------------------------
// tf32 GEMM (attention only: scores + AV)
// ---------------------------------------------------------------------------
enum GemmMode { M_SCORES = 0, M_AV, M_GATE };

struct GemmP {
  int mode;
  const float* A;
  const float* Bm;
  float* C;
  __half* C16;
  int M, N, K, lda, ldb, ldc;
  int transB;
};

constexpr int APAD = 20;
constexpr int BPAD = 136;
constexpr int STAGES = 4;
constexpr int STW = 128 * APAD;
constexpr int GEMM_DSMEM = STAGES * 2 * STW * 4;

extern __shared__ uint32_t dynsmem[];

__global__ __launch_bounds__(256, 2) void gemm_tc(GemmP p) {
  int z = blockIdx.z;
  const float* Ab = p.A;
  const float* Bb = p.Bm;
  float* Cb = p.C;
  __half* Cb16 = p.C16;
  int Meff = p.M;

  if (p.mode == M_SCORES) {
    int b = z >> 3, h = z & 7;
    Ab = p.A + ((size_t)(b * S) * NH + h) * D;
    Bb = p.Bm + ((size_t)(b * S) * NKV + (h >> 2)) * D;
    Cb = p.C + (size_t)z * S * S;
  } else if (p.mode == M_AV) {
    int b = z >> 3, h = z & 7;
    Ab = p.A + (size_t)z * S * S;
    Bb = p.Bm + (size_t)(b * S) * QKVW + (size_t)(NH + NKV) * D + (h >> 2) * D;
    Cb = p.C + (size_t)(b * S) * (NH * D) + h * D;
    Cb16 = p.C16 + (size_t)(b * S) * (NH * D) + h * D;
  }

  int m0 = blockIdx.y * 128, n0 = blockIdx.x * 128;
  if (m0 >= Meff) return;
  if (p.mode == M_SCORES && n0 > m0 + 127) return;

  int kend = p.K;
  if (p.mode == M_AV) kend = min(p.K, m0 + 128);
  int nk = kend >> 4;

  uint32_t* Asm = dynsmem;
  uint32_t* Bsm = dynsmem + STAGES * STW;

  int tid = threadIdx.x;
  int lane = tid & 31, wid = tid >> 5;
  int warp_m = wid & 1, warp_n = wid >> 1;
  int gid = lane >> 2, tig = lane & 3;

  uint32_t as_base = (uint32_t)__cvta_generic_to_shared(Asm);
  uint32_t bs_base = (uint32_t)__cvta_generic_to_shared(Bsm);
  int lm_row = (lane & 15);
  int lm_col = (lane >> 4) << 2;

  float acc[4][4][4];
#pragma unroll
  for (int a = 0; a < 4; a++)
#pragma unroll
    for (int b = 0; b < 4; b++)
#pragma unroll
      for (int c = 0; c < 4; c++) acc[a][b][c] = 0.f;

  int a_row0 = tid >> 2, a_kq = (tid & 3) * 4;
  const float* a_src0;
  const float* a_src1;
  {
    int gm0 = m0 + a_row0, gm1 = m0 + a_row0 + 64;
    a_src0 = (gm0 < Meff) ? Ab + (size_t)gm0 * p.lda : Ab;
    a_src1 = (gm1 < Meff) ? Ab + (size_t)gm1 * p.lda : Ab;
  }
  bool a_v0 = (m0 + a_row0) < Meff;
  bool a_v1 = (m0 + a_row0 + 64) < Meff;

  auto issue = [&](int it, int st) {
    if (it < nk) {
      int k0 = it << 4;
      cp_async16(as_base + (uint32_t)(st * STW + a_row0 * APAD + a_kq) * 4u,
                 a_src0 + k0 + a_kq, a_v0);
      cp_async16(
          as_base + (uint32_t)(st * STW + (a_row0 + 64) * APAD + a_kq) * 4u,
          a_src1 + k0 + a_kq, a_v1);
      if (p.transB) {
        int n = tid >> 2, kq = (tid & 3) * 4;
        cp_async16(bs_base + (uint32_t)(st * STW + n * APAD + kq) * 4u,
                   Bb + (size_t)(n0 + n) * p.ldb + k0 + kq, true);
        cp_async16(bs_base + (uint32_t)(st * STW + (n + 64) * APAD + kq) * 4u,
                   Bb + (size_t)(n0 + n + 64) * p.ldb + k0 + kq, true);
      } else {
        int kk = tid >> 5, nq = (tid & 31) * 4;
        cp_async16(bs_base + (uint32_t)(st * STW + kk * BPAD + nq) * 4u,
                   Bb + (size_t)(k0 + kk) * p.ldb + n0 + nq, true);
        cp_async16(bs_base + (uint32_t)(st * STW + (kk + 8) * BPAD + nq) * 4u,
                   Bb + (size_t)(k0 + kk + 8) * p.ldb + n0 + nq, true);
      }
    }
    cp_commit();
  };

  issue(0, 0);
  issue(1, 1);
  issue(2, 2);

  int cur = 0;
  for (int it = 0; it < nk; it++) {
    cp_wait<STAGES - 2>();
    __syncthreads();
    issue(it + 3, (cur + 3) & (STAGES - 1));

    const uint32_t* Bsp = Bsm + cur * STW;
#pragma unroll
    for (int ks = 0; ks < 16; ks += 8) {
      uint32_t afr[4][4];
#pragma unroll
      for (int mt = 0; mt < 4; mt++) {
        int row = warp_m * 64 + mt * 16 + lm_row;
        uint32_t saddr =
            as_base + (uint32_t)(cur * STW + row * APAD + ks + lm_col) * 4u;
        ldsm4(afr[mt], saddr);
      }
      uint32_t bfr[4][2];
      if (p.transB) {
#pragma unroll
        for (int nt = 0; nt < 4; nt++) {
          int ncol = warp_n * 32 + nt * 8 + gid;
          bfr[nt][0] = Bsp[ncol * APAD + ks + tig];
          bfr[nt][1] = Bsp[ncol * APAD + ks + tig + 4];
        }
      } else {
#pragma unroll
        for (int nt = 0; nt < 4; nt++) {
          int ncol = warp_n * 32 + nt * 8 + gid;
          bfr[nt][0] = Bsp[(ks + tig) * BPAD + ncol];
          bfr[nt][1] = Bsp[(ks + tig + 4) * BPAD + ncol];
        }
      }
#pragma unroll
      for (int mt = 0; mt < 4; mt++)
#pragma unroll
        for (int nt = 0; nt < 4; nt++) mma_tf32(acc[mt][nt], afr[mt], bfr[nt]);
    }
    cur = (cur + 1) & (STAGES - 1);
  }

#pragma unroll
  for (int mt = 0; mt < 4; mt++) {
#pragma unroll
    for (int nt = 0; nt < 4; nt++) {
#pragma unroll
      for (int ee = 0; ee < 4; ee++) {
        int gm = m0 + warp_m * 64 + mt * 16 + gid + (ee >= 2 ? 8 : 0);
        int gn = n0 + warp_n * 32 + nt * 8 + tig * 2 + (ee & 1);
        if (gm >= Meff) continue;
        float v = acc[mt][nt][ee];
        if (p.mode == M_SCORES) {
          if (gn > gm) continue;
          v *= SCALE;
        }
        Cb[(size_t)gm * p.ldc + gn] = v;
        if (p.mode == M_AV) Cb16[(size_t)gm * p.ldc + gn] = __float2half(v);
      }
    }
  }
}

// ---------------------------------------------------------------------------
// Unified fp16 GEMM.
// Modes: FM_GU (fused SiLU -> fp16, optional gather, interleaved gate/up B),
//        FM_DN (scatter-atomic into comb), FM_QKV (transB + bias),
//        FM_WO (transB + resid), FM_SDN (NN plain fp32).
// A: fp16 global, cp.async -> [m][40] smem, ldmatrix.x4.
// B: fp32 weights, LDG+convert into packed k-pair words [kp][136].
// ---------------------------------------------------------------------------
enum F16Mode { FM_GU = 0, FM_DN, FM_QKV, FM_WO, FM_SDN };

struct F16P {
  int mode;
  const __half* A;
  const float* Bm;
  __half* Ch;
  float* Cf;
  const float* bias;
  const float* resid;
  const int* gidx;
  const int* cnt;
  const float* wslot;
  int lda, ldb, ldc, K, M;
  long long a_zs, b_zs, c_zs;
  int transB;
};

constexpr int HAPAD = 40;
constexpr int F16_ASTW = 128 * HAPAD;
constexpr int F16_BSTW = 16 * 136;

__global__ __launch_bounds__(256, 2) void gemm_f16(F16P p) {
  int z = blockIdx.z;
  int Meff = p.cnt ? min(p.cnt[z], CAP) : p.M;
  int m0 = blockIdx.y * 128;
  if (m0 >= Meff) return;

  const __half* Ab = p.A + (size_t)z * p.a_zs;
  const float* Bb = p.Bm + (size_t)z * p.b_zs;
  const int* gidx = (p.mode == FM_GU && p.gidx) ? p.gidx + z * CAP : nullptr;
  const int* tokz = (p.mode == FM_DN) ? p.gidx + z * CAP : nullptr;
  const float* wz = (p.mode == FM_DN) ? p.wslot + z * CAP : nullptr;
  int n0 = blockIdx.x * 128;   // generic modes
  int n0g = blockIdx.x * 64;   // FM_GU column base

  __shared__ __half Ash[2][F16_ASTW];
  __shared__ uint32_t Bsh[2][F16_BSTW];

  int tid = threadIdx.x;
  int lane = tid & 31, wid = tid >> 5;
  int warp_m = wid & 1, warp_n = wid >> 1;
  int gid = lane >> 2, tig = lane & 3;

  uint32_t as_base = (uint32_t)__cvta_generic_to_shared(&Ash[0][0]);

  int nk = p.K >> 5;

  float acc[4][4][4];
#pragma unroll
  for (int a = 0; a < 4; a++)
#pragma unroll
    for (int b = 0; b < 4; b++)
#pragma unroll
      for (int c = 0; c < 4; c++) acc[a][b][c] = 0.f;

  int a_row0 = tid >> 2, a_kq = (tid & 3) * 8;
  const __half* a_src0;
  const __half* a_src1;
  {
    int gm0 = m0 + a_row0, gm1 = m0 + a_row0 + 64;
    a_src0 = (gm0 < Meff)
                 ? (gidx ? Ab + (size_t)gidx[gm0] * p.lda
                         : Ab + (size_t)gm0 * p.lda)
                 : Ab;
    a_src1 = (gm1 < Meff)
                 ? (gidx ? Ab + (size_t)gidx[gm1] * p.lda
                         : Ab + (size_t)gm1 * p.lda)
                 : Ab;
  }
  bool a_v0 = (m0 + a_row0) < Meff;
  bool a_v1 = (m0 + a_row0 + 64) < Meff;

  auto issueA = [&](int it, int st) {
    if (it < nk) {
      int k0h = it << 5;
      cp_async16(
          as_base + (uint32_t)(st * F16_ASTW + a_row0 * HAPAD + a_kq) * 2u,
          a_src0 + k0h + a_kq, a_v0);
      cp_async16(
          as_base +
              (uint32_t)(st * F16_ASTW + (a_row0 + 64) * HAPAD + a_kq) * 2u,
          a_src1 + k0h + a_kq, a_v1);
    }
    cp_commit();
  };

  // ---- B loader ----
  uint32_t bstage[8];
  // NN mapping (FM_GU interleave or plain): idx -> kp = idx>>5, n4 = (idx&31)*4
  int nn_kp0 = tid >> 5, nn_nq0 = (tid & 31) * 4;
  int nn_kp1 = (tid + 256) >> 5, nn_nq1 = ((tid + 256) & 31) * 4;
  auto bcol = [&](int n) -> int {
    if (p.mode == FM_GU) {
      int grp = n >> 4;
      int isup = (n >> 3) & 1;
      int cc = grp * 8 + (n & 7);
      return (isup ? FI : 0) + n0g + cc;  // FI == FSH
    }
    return n0 + n;
  };
  int nn_c0 = bcol(nn_nq0);
  int nn_c1 = bcol(nn_nq1);
  // transB mapping: idx -> n = idx>>2, kf = (idx&3)*8 floats (kp base = kf/2)
  int tb_n0 = tid >> 2, tb_kf0 = (tid & 3) * 8;
  int tb_n1 = (tid + 256) >> 2, tb_kf1 = ((tid + 256) & 3) * 8;

  auto loadB = [&](int it) {
    if (it >= nk) return;
    int k0 = it << 5;
    if (p.transB) {
      const float* r0 = Bb + (size_t)(n0 + tb_n0) * p.ldb + k0 + tb_kf0;
      float4 f0 = *(const float4*)r0;
      float4 f1 = *(const float4*)(r0 + 4);
      bstage[0] = h2u(__floats2half2_rn(f0.x, f0.y));
      bstage[1] = h2u(__floats2half2_rn(f0.z, f0.w));
      bstage[2] = h2u(__floats2half2_rn(f1.x, f1.y));
      bstage[3] = h2u(__floats2half2_rn(f1.z, f1.w));
      const float* r2 = Bb + (size_t)(n0 + tb_n1) * p.ldb + k0 + tb_kf1;
      float4 f2 = *(const float4*)r2;
      float4 f3 = *(const float4*)(r2 + 4);
      bstage[4] = h2u(__floats2half2_rn(f2.x, f2.y));
      bstage[5] = h2u(__floats2half2_rn(f2.z, f2.w));
      bstage[6] = h2u(__floats2half2_rn(f3.x, f3.y));
      bstage[7] = h2u(__floats2half2_rn(f3.z, f3.w));
    } else {
      const float* r0 = Bb + (size_t)(k0 + 2 * nn_kp0) * p.ldb + nn_c0;
      float4 f0 = *(const float4*)r0;
      float4 f1 = *(const float4*)(r0 + p.ldb);
      bstage[0] = h2u(__floats2half2_rn(f0.x, f1.x));
      bstage[1] = h2u(__floats2half2_rn(f0.y, f1.y));
      bstage[2] = h2u(__floats2half2_rn(f0.z, f1.z));
      bstage[3] = h2u(__floats2half2_rn(f0.w, f1.w));
      const float* r2 = Bb + (size_t)(k0 + 2 * nn_kp1) * p.ldb + nn_c1;
      float4 f2 = *(const float4*)r2;
      float4 f3 = *(const float4*)(r2 + p.ldb);
      bstage[4] = h2u(__floats2half2_rn(f2.x, f3.x));
      bstage[5] = h2u(__floats2half2_rn(f2.y, f3.y));
      bstage[6] = h2u(__floats2half2_rn(f2.z, f3.z));
      bstage[7] = h2u(__floats2half2_rn(f2.w, f3.w));
    }
  };
  auto storeB = [&](int it, int st) {
    if (it >= nk) return;
    if (p.transB) {
      int kp0 = tb_kf0 >> 1;
      Bsh[st][(kp0 + 0) * 136 + tb_n0] = bstage[0];
      Bsh[st][(kp0 + 1) * 136 + tb_n0] = bstage[1];
      Bsh[st][(kp0 + 2) * 136 + tb_n0] = bstage[2];
      Bsh[st][(kp0 + 3) * 136 + tb_n0] = bstage[3];
      int kp1 = tb_kf1 >> 1;
      Bsh[st][(kp1 + 0) * 136 + tb_n1] = bstage[4];
      Bsh[st][(kp1 + 1) * 136 + tb_n1] = bstage[5];
      Bsh[st][(kp1 + 2) * 136 + tb_n1] = bstage[6];
      Bsh[st][(kp1 + 3) * 136 + tb_n1] = bstage[7];
    } else {
      uint32_t* d0 = &Bsh[st][nn_kp0 * 136 + nn_nq0];
      d0[0] = bstage[0];
      d0[1] = bstage[1];
      d0[2] = bstage[2];
      d0[3] = bstage[3];
      uint32_t* d1 = &Bsh[st][nn_kp1 * 136 + nn_nq1];
      d1[0] = bstage[4];
      d1[1] = bstage[5];
      d1[2] = bstage[6];
      d1[3] = bstage[7];
    }
  };

  issueA(0, 0);
  loadB(0);
  storeB(0, 0);
  cp_wait<0>();
  __syncthreads();

  int cur = 0;
  for (int it = 0; it < nk; it++) {
    issueA(it + 1, cur ^ 1);
    loadB(it + 1);

    const uint32_t* Bsp = &Bsh[cur][0];
#pragma unroll
    for (int ks = 0; ks < 2; ks++) {
      uint32_t afr[4][4];
#pragma unroll
      for (int mt = 0; mt < 4; mt++) {
        int row = warp_m * 64 + mt * 16 + (lane & 15);
        uint32_t saddr =
            as_base + (uint32_t)(cur * F16_ASTW + row * HAPAD + ks * 16 +
                                 ((lane >> 4) << 3)) *
                          2u;
        ldsm4(afr[mt], saddr);
      }
      uint32_t bfr[4][2];
      int kpb = ks * 8;
#pragma unroll
      for (int nt = 0; nt < 4; nt++) {
        int ncol = warp_n * 32 + nt * 8 + gid;
        bfr[nt][0] = Bsp[(kpb + tig) * 136 + ncol];
        bfr[nt][1] = Bsp[(kpb + 4 + tig) * 136 + ncol];
      }
#pragma unroll
      for (int mt = 0; mt < 4; mt++)
#pragma unroll
        for (int nt = 0; nt < 4; nt++) mma_f16(acc[mt][nt], afr[mt], bfr[nt]);
    }

    storeB(it + 1, cur ^ 1);
    cp_wait<0>();
    __syncthreads();
    cur ^= 1;
  }

  if (p.mode == FM_GU) {
    __half* Chb = p.Ch + (size_t)z * p.c_zs;
#pragma unroll
    for (int mt = 0; mt < 4; mt++) {
#pragma unroll
      for (int q = 0; q < 2; q++) {
#pragma unroll
        for (int half_e = 0; half_e < 2; half_e++) {
          int gm = m0 + warp_m * 64 + mt * 16 + gid + half_e * 8;
          if (gm >= Meff) continue;
          float g0 = acc[mt][2 * q][half_e * 2 + 0];
          float g1 = acc[mt][2 * q][half_e * 2 + 1];
          float u0 = acc[mt][2 * q + 1][half_e * 2 + 0];
          float u1 = acc[mt][2 * q + 1][half_e * 2 + 1];
          float a0 = (g0 / (1.f + expf(-g0))) * u0;
          float a1 = (g1 / (1.f + expf(-g1))) * u1;
          int cc = n0g + (2 * warp_n + q) * 8 + tig * 2;
          __half2 h = __floats2half2_rn(a0, a1);
          *(__half2*)&Chb[(size_t)gm * p.ldc + cc] = h;
        }
      }
    }
  } else if (p.mode == FM_DN) {
#pragma unroll
    for (int mt = 0; mt < 4; mt++) {
#pragma unroll
      for (int nt = 0; nt < 4; nt++) {
#pragma unroll
        for (int ee = 0; ee < 4; ee++) {
          int gm = m0 + warp_m * 64 + mt * 16 + gid + (ee >= 2 ? 8 : 0);
          if (gm >= Meff) continue;
          int gn = n0 + warp_n * 32 + nt * 8 + tig * 2 + (ee & 1);
          int t = tokz[gm];
          float w = wz[gm];
          atomicAdd(&p.Cf[(size_t)t * p.ldc + gn], acc[mt][nt][ee] * w);
        }
      }
    }
  } else {
#pragma unroll
    for (int mt = 0; mt < 4; mt++) {
#pragma unroll
      for (int nt = 0; nt < 4; nt++) {
#pragma unroll
        for (int ee = 0; ee < 4; ee++) {
          int gm = m0 + warp_m * 64 + mt * 16 + gid + (ee >= 2 ? 8 : 0);
          if (gm >= Meff) continue;
          int gn = n0 + warp_n * 32 + nt * 8 + tig * 2 + (ee & 1);
          float v = acc[mt][nt][ee];
          if (p.mode == FM_QKV)
            v += p.bias[gn];
          else if (p.mode == FM_WO)
            v += p.resid[(size_t)gm * p.ldc + gn];
          p.Cf[(size_t)gm * p.ldc + gn] = v;
        }
      }
    }
  }
}

// ---------------------------------------------------------------------------
// fp32 SIMT GEMM (tiny gate GEMM -> exact routing inputs)
// ---------------------------------------------------------------------------
__global__ __launch_bounds__(256) void gemm_kernel(GemmP p) {
  const float* Ab = p.A;
  const float* Bb = p.Bm;
  float* Cb = p.C;
  int Meff = p.M;

  int m0 = blockIdx.y * 64, n0 = blockIdx.x * 64;
  if (m0 >= Meff) return;

  __shared__ float As[16][68];
  __shared__ float Bs[16][68];
  int tid = threadIdx.x, tx = tid & 15, ty = tid >> 4;
  float acc[4][4] = {};

  for (int k0 = 0; k0 < p.K; k0 += 16) {
#pragma unroll
    for (int l = 0; l < 4; l++) {
      int i = tid + l * 256;
      int row = i >> 4, col = i & 15;
      int gm = m0 + row;
      float v = 0.f;
      if (gm < Meff) v = Ab[(size_t)gm * p.lda + k0 + col];
      As[col][row] = v;
    }
#pragma unroll
    for (int l = 0; l < 4; l++) {
      int i = tid + l * 256;
      if (p.transB) {
        int col = i >> 4, kk = i & 15;
        Bs[kk][col] = Bb[(size_t)(n0 + col) * p.ldb + (k0 + kk)];
      } else {
        int kk = i >> 6, col = i & 63;
        Bs[kk][col] = Bb[(size_t)(k0 + kk) * p.ldb + (n0 + col)];
      }
    }
    __syncthreads();
#pragma unroll
    for (int kk = 0; kk < 16; kk++) {
      float4 a4 = *(const float4*)(&As[kk][ty * 4]);
      float4 b4 = *(const float4*)(&Bs[kk][tx * 4]);
      float av[4] = {a4.x, a4.y, a4.z, a4.w};
      float bv[4] = {b4.x, b4.y, b4.z, b4.w};
#pragma unroll
      for (int i = 0; i < 4; i++)
#pragma unroll
        for (int j = 0; j < 4; j++) acc[i][j] += av[i] * bv[j];
    }
    __syncthreads();
  }

#pragma unroll
  for (int i = 0; i < 4; i++) {
    int gm = m0 + ty * 4 + i;
    if (gm >= Meff) continue;
#pragma unroll
    for (int j = 0; j < 4; j++) {
      int gn = n0 + tx * 4 + j;
      Cb[(size_t)gm * p.ldc + gn] = acc[i][j];
    }
  }
}

// ---------------------------------------------------------------------------
// Row softmax, causal-aware.
// ---------------------------------------------------------------------------
__global__ void softmax_kernel(float* __restrict__ sc) {
  size_t row = blockIdx.x;
  int q = (int)(row & (S - 1));
  int len = q + 1;
  int fill_end = ((q >> 7) + 1) << 7;
  float* p = sc + row * (size_t)S;
  __shared__ float red[8];
  float mx = -INFINITY;
  for (int i = threadIdx.x; i < len; i += 256) mx = fmaxf(mx, p[i]);
  for (int o = 16; o; o >>= 1) mx = fmaxf(mx, __shfl_xor_sync(~0u, mx, o));
  if ((threadIdx.x & 31) == 0) red[threadIdx.x >> 5] = mx;
  __syncthreads();
  if (threadIdx.x == 0) {
    float m = red[0];
    for (int i = 1; i < 8; i++) m = fmaxf(m, red[i]);
    red[0] = m;
  }
  __syncthreads();
  mx = red[0];
  __syncthreads();
  float sum = 0.f;
  for (int i = threadIdx.x; i < len; i += 256) {
    float e = expf(p[i] - mx);
    p[i] = e;
    sum += e;
  }
  for (int o = 16; o; o >>= 1) sum += __shfl_xor_sync(~0u, sum, o);
  if ((threadIdx.x & 31) == 0) red[threadIdx.x >> 5] = sum;
  __syncthreads();
  if (threadIdx.x == 0) {
    float t = 0.f;
    for (int i = 0; i < 8; i++) t += red[i];
    red[0] = t;
  }
  __syncthreads();
  float inv = 1.f / red[0];
  for (int i = threadIdx.x; i < len; i += 256) p[i] *= inv;
  for (int i = len + threadIdx.x; i < fill_end; i += 256) p[i] = 0.f;
}

// ---------------------------------------------------------------------------
// Routing
// ---------------------------------------------------------------------------
__global__ void route_kernel(const float* __restrict__ logits,
                             const float* __restrict__ gate_b,
                             int* __restrict__ topi, float* __restrict__ fw) {
  int t = blockIdx.x * blockDim.x + threadIdx.x;
  if (t >= T) return;
  float corr[E];
  const float* lg = logits + (size_t)t * E;
  for (int e = 0; e < E; e++) {
    float s = 1.f / (1.f + expf(-lg[e]));
    corr[e] = s + gate_b[e];
  }
  float grp[NG];
  for (int g = 0; g < NG; g++) {
    float m1 = -INFINITY, m2 = -INFINITY;
    for (int i = 0; i < E / NG; i++) {
      float v = corr[g * (E / NG) + i];
      if (v > m1) {
        m2 = m1;
        m1 = v;
      } else if (v > m2) {
        m2 = v;
      }
    }
    grp[g] = m1 + m2;
  }
  unsigned gsel = 0;
  for (int it = 0; it < TG; it++) {
    float best = -INFINITY;
    int bi = 0;
    for (int g = 0; g < NG; g++)
      if (!((gsel >> g) & 1u) && grp[g] > best) {
        best = grp[g];
        bi = g;
      }
    gsel |= 1u << bi;
  }
  unsigned long long esel = 0ull;
  int sel[TK];
  float ws[TK];
  float wsum = 0.f;
  for (int it = 0; it < TK; it++) {
    float best = -INFINITY;
    int bi = 0;
    for (int e = 0; e < E; e++) {
      if (!((gsel >> (e >> 3)) & 1u)) continue;
      if ((esel >> e) & 1ull) continue;
      if (corr[e] > best) {
        best = corr[e];
        bi = e;
      }
    }
    esel |= 1ull << bi;
    sel[it] = bi;
    float s = corr[bi] - gate_b[bi];
    ws[it] = s;
    wsum += s;
  }
  float inv = 1.f / wsum;
  for (int j = 0; j < TK; j++) {
    topi[t * TK + j] = sel[j];
    fw[t * TK + j] = ws[j] * inv;
  }
}

__global__ void zero_cnt_kernel(int* __restrict__ cnt) {
  if (threadIdx.x < E) cnt[threadIdx.x] = 0;
}

__global__ void assign_kernel(const int* __restrict__ topi,
                              const float* __restrict__ fw,
                              int* __restrict__ cnt, int* __restrict__ tok,
                              float* __restrict__ wslot) {
  int i = blockIdx.x * blockDim.x + threadIdx.x;
  if (i >= T * TK) return;
  int e = topi[i];
  int p = atomicAdd(&cnt[e], 1);
  if (p < CAP) {
    tok[e * CAP + p] = i / TK;
    wslot[e * CAP + p] = fw[i];
  }
}

// ---------------------------------------------------------------------------
// Final: out = h2 + comb
// ---------------------------------------------------------------------------
__global__ void final_kernel(const float* __restrict__ h2,
                             const float* __restrict__ comb,
                             float* __restrict__ out) {
  size_t i = (size_t)blockIdx.x * 256 + threadIdx.x;
  if (i < (size_t)T * H) out[i] = h2[i] + comb[i];
}

// ---------------------------------------------------------------------------
// Host launcher
// ---------------------------------------------------------------------------
extern "C" void kernel_launch(void* const* d_in, const int* in_sizes, int n_in,
                              void* d_out, int out_size) {
  const float* x = (const float*)d_in[0];
  const int* positions = (const int*)d_in[1];
  const float* ln1_w = (const float*)d_in[2];
  const float* ln2_w = (const float*)d_in[3];
  const float* wqkv = (const float*)d_in[4];
  const float* bqkv = (const float*)d_in[5];
  const float* qn_w = (const float*)d_in[6];
  const float* kn_w = (const float*)d_in[7];
  const float* wo = (const float*)d_in[8];
  const float* gate_w = (const float*)d_in[9];
  const float* gate_b = (const float*)d_in[10];
  const float* w_gu = (const float*)d_in[11];
  const float* w_dn = (const float*)d_in[12];
  const float* sw_gu = (const float*)d_in[13];
  const float* sw_dn = (const float*)d_in[14];
  float* out = (float*)d_out;

  static bool attr_set = false;
  if (!attr_set) {
    cudaFuncSetAttribute(gemm_tc, cudaFuncAttributeMaxDynamicSharedMemorySize,
                         GEMM_DSMEM);
    attr_set = true;
  }

  float* scr = nullptr;
  cudaGetSymbolAddress((void**)&scr, g_scratch);
  int* topi = nullptr;
  cudaGetSymbolAddress((void**)&topi, g_topi);
  int* cnt = nullptr;
  cudaGetSymbolAddress((void**)&cnt, g_cnt);
  int* tok = nullptr;
  cudaGetSymbolAddress((void**)&tok, g_tok);
  float* wslot = nullptr;
  cudaGetSymbolAddress((void**)&wslot, g_wslot);
  __half* xt16 = nullptr;
  cudaGetSymbolAddress((void**)&xt16, g_xt16);
  __half* bh16 = nullptr;
  cudaGetSymbolAddress((void**)&bh16, g_bh16);
  __half* aout16 = nullptr;
  cudaGetSymbolAddress((void**)&aout16, g_aout16);
  __half* shact16 = nullptr;
  cudaGetSymbolAddress((void**)&shact16, g_shact16);
  __half* act16 = nullptr;
  cudaGetSymbolAddress((void**)&act16, g_act16);

  float* bh = scr + OFF_H;
  float* bqkvb = scr + OFF_QKV;
  float* bq = scr + OFF_Q;
  float* bk = scr + OFF_K;
  float* bsc = scr + OFF_SC;
  float* baout = scr + OFF_AOUT;
  float* bh2 = scr + OFF_H2;
  float* bxt = scr + OFF_XT;
  float* blog = scr + OFF_LOG;
  float* bfw = scr + OFF_FW;
  float* bcomb = scr + OFF_COMB;

  // 1. rmsnorm1 (fp32 + fp16)
  rmsnorm_kernel<<<T, 256>>>(x, ln1_w, bh, bh16, H);

  // 2. qkv = h @ wqkv^T + b  (fp16)
  {
    F16P p{};
    p.mode = FM_QKV;
    p.A = bh16; p.Bm = wqkv; p.Cf = bqkvb; p.bias = bqkv;
    p.lda = H; p.ldb = H; p.ldc = QKVW; p.K = H; p.M = T;
    p.transB = 1;
    gemm_f16<<<dim3(QKVW / 128, T / 128, 1), 256>>>(p);
  }

  // 3. q/k rmsnorm + rope
  qknorm_rope_kernel<<<dim3(T, NH + NKV), 128>>>(bqkvb, positions, qn_w, kn_w,
                                                 bq, bk);

  // 4. scores (tf32)
  {
    GemmP p{};
    p.mode = M_SCORES;
    p.A = bq; p.Bm = bk; p.C = bsc;
    p.M = S; p.N = S; p.K = D;
    p.lda = NH * D; p.ldb = NKV * D; p.ldc = S; p.transB = 1;
    gemm_tc<<<dim3(S / 128, S / 128, B * NH), 256, GEMM_DSMEM>>>(p);
  }

  // 5. softmax
  softmax_kernel<<<B * NH * S, 256>>>(bsc);

  // 6. attn @ v (tf32; dual fp32+fp16 out)
  {
    GemmP p{};
    p.mode = M_AV;
    p.A = bsc; p.Bm = bqkvb; p.C = baout; p.C16 = aout16;
    p.M = S; p.N = D; p.K = S;
    p.lda = S; p.ldb = QKVW; p.ldc = NH * D; p.transB = 0;
    gemm_tc<<<dim3(D / 128, S / 128, B * NH), 256, GEMM_DSMEM>>>(p);
  }

  // 7. h2 = x + aout @ wo^T  (fp16)
  {
    F16P p{};
    p.mode = FM_WO;
    p.A = aout16; p.Bm = wo; p.Cf = bh2; p.resid = x;
    p.lda = NH * D; p.ldb = NH * D; p.ldc = H; p.K = NH * D; p.M = T;
    p.transB = 1;
    gemm_f16<<<dim3(H / 128, T / 128, 1), 256>>>(p);
  }

  // 8. rmsnorm2 (fp32 + fp16)
  rmsnorm_kernel<<<T, 256>>>(bh2, ln2_w, bxt, xt16, H);

  // 9. gate logits (exact fp32)
  {
    GemmP p{};
    p.mode = M_GATE;
    p.A = bxt; p.Bm = gate_w; p.C = blog;
    p.M = T; p.N = E; p.K = H;
    p.lda = H; p.ldb = H; p.ldc = E; p.transB = 1;
    gemm_kernel<<<dim3(1, T / 64, 1), 256>>>(p);
  }

  // 10. routing
  route_kernel<<<T / 256, 256>>>(blog, gate_b, topi, bfw);
  zero_cnt_kernel<<<1, 64>>>(cnt);
  assign_kernel<<<(T * TK) / 256, 256>>>(topi, bfw, cnt, tok, wslot);

  // 11. shared expert: fused up-gate+SiLU (fp16) -> shact16
  {
    F16P p{};
    p.mode = FM_GU;
    p.A = xt16; p.Bm = sw_gu; p.Ch = shact16;
    p.lda = H; p.ldb = 2 * FSH; p.ldc = FSH; p.K = H; p.M = T;
    p.a_zs = 0; p.b_zs = 0; p.c_zs = 0;
    gemm_f16<<<dim3(FSH / 64, T / 128, 1), 256>>>(p);
  }
  // 11b. shared down -> bcomb (plain fp32 out; precedes MoE scatter)
  {
    F16P p{};
    p.mode = FM_SDN;
    p.A = shact16; p.Bm = sw_dn; p.Cf = bcomb;
    p.lda = FSH; p.ldb = H; p.ldc = H; p.K = FSH; p.M = T;
    gemm_f16<<<dim3(H / 128, T / 128, 1), 256>>>(p);
  }

  // 12. MoE up-gate (fp16) fused SiLU -> act16
  {
    F16P p{};
    p.mode = FM_GU;
    p.A = xt16; p.Bm = w_gu; p.Ch = act16;
    p.gidx = tok; p.cnt = cnt;
    p.lda = H; p.ldb = 2 * FI; p.ldc = FI; p.K = H; p.M = CAP;
    p.a_zs = 0; p.b_zs = (long long)H * 2 * FI; p.c_zs = (long long)CAP * FI;
    gemm_f16<<<dim3(FI / 64, CAP / 128, E), 256>>>(p);
  }

  // 13. MoE down (fp16), scatter-accumulate into bcomb
  {
    F16P p{};
    p.mode = FM_DN;
    p.A = act16; p.Bm = w_dn; p.Cf = bcomb;
    p.gidx = tok; p.cnt = cnt; p.wslot = wslot;
    p.lda = FI; p.ldb = H; p.ldc = H; p.K = FI; p.M = CAP;
    p.a_zs = (long long)CAP * FI; p.b_zs = (long long)FI * H; p.c_zs = 0;
    gemm_f16<<<dim3(H / 128, CAP / 128, E), 256>>>(p);
  }

  // 14. out = h2 + comb
  final_kernel<<<(int)(((size_t)T * H + 255) / 256), 256>>>(bh2, bcomb, out);
}

// round 10
// speedup vs baseline: 1.2107x; 1.0058x over previous
#include <cuda_runtime.h>
#include <cuda_fp16.h>
#include <math.h>
#include <stdint.h>

namespace cfg {
constexpr int B = 2, S = 1024, H = 1024;
constexpr int NH = 8, NKV = 2, D = 128, ROT = 64;
constexpr int E = 64, TK = 8, NG = 8, TG = 4;
constexpr int FI = 512, FSH = 512, CAP = 512;
constexpr int T = B * S;
constexpr int QKVW = (NH + 2 * NKV) * D;  // 1536
constexpr float EPS = 1e-5f;
constexpr float SCALE = 0.08838834764831843f;
constexpr float THETA = 10000.0f;
}  // namespace cfg
using namespace cfg;

// ---------------------------------------------------------------------------
// Static device scratch
// ---------------------------------------------------------------------------
constexpr size_t N_H    = (size_t)T * H;
constexpr size_t N_QKV  = (size_t)T * QKVW;
constexpr size_t N_Q    = (size_t)T * NH * D;
constexpr size_t N_K    = (size_t)T * NKV * D;
constexpr size_t N_SC   = (size_t)B * NH * S * S;
constexpr size_t N_AOUT = (size_t)T * NH * D;
constexpr size_t N_H2   = (size_t)T * H;
constexpr size_t N_XT   = (size_t)T * H;
constexpr size_t N_LOG  = (size_t)T * E;
constexpr size_t N_FW   = (size_t)T * TK;
constexpr size_t N_COMB = (size_t)T * H;

constexpr size_t OFF_H    = 0;
constexpr size_t OFF_QKV  = OFF_H + N_H;
constexpr size_t OFF_Q    = OFF_QKV + N_QKV;
constexpr size_t OFF_K    = OFF_Q + N_Q;
constexpr size_t OFF_SC   = OFF_K + N_K;
constexpr size_t OFF_AOUT = OFF_SC + N_SC;
constexpr size_t OFF_H2   = OFF_AOUT + N_AOUT;
constexpr size_t OFF_XT   = OFF_H2 + N_H2;
constexpr size_t OFF_LOG  = OFF_XT + N_XT;
constexpr size_t OFF_FW   = OFF_LOG + N_LOG;
constexpr size_t OFF_COMB = OFF_FW + N_FW;
constexpr size_t SCRATCH_F = OFF_COMB + N_COMB;

__device__ float g_scratch[SCRATCH_F];
__device__ __half g_xt16[(size_t)T * H];
__device__ __half g_bh16[(size_t)T * H];
__device__ __half g_aout16[(size_t)T * NH * D];
__device__ __half g_shact16[(size_t)T * FSH];
__device__ __half g_act16[(size_t)E * CAP * FI];

// packed fp16 weights: word[kp][n] = (w[2kp][n], w[2kp+1][n])
__device__ uint32_t g_wgu16[(size_t)E * (H / 2) * (2 * FI)];
__device__ uint32_t g_wdn16[(size_t)E * (FI / 2) * H];
__device__ uint32_t g_wqkv16[(size_t)(H / 2) * QKVW];      // transposed
__device__ uint32_t g_wo16[(size_t)(NH * D / 2) * H];      // transposed
__device__ uint32_t g_sgu16[(size_t)(H / 2) * (2 * FSH)];
__device__ uint32_t g_sdn16[(size_t)(FSH / 2) * H];

__device__ int g_topi[T * TK];
__device__ int g_cnt[E];
__device__ int g_tok[E * CAP];
__device__ float g_wslot[E * CAP];

// ---------------------------------------------------------------------------
// helpers
// ---------------------------------------------------------------------------
__device__ __forceinline__ uint32_t h2u(__half2 h) {
  return *reinterpret_cast<uint32_t*>(&h);
}

__device__ __forceinline__ void mma_tf32(float c[4], const uint32_t a[4],
                                         const uint32_t b[2]) {
  asm volatile(
      "mma.sync.aligned.m16n8k8.row.col.f32.tf32.tf32.f32 "
      "{%0,%1,%2,%3}, {%4,%5,%6,%7}, {%8,%9}, {%0,%1,%2,%3};\n"
      : "+f"(c[0]), "+f"(c[1]), "+f"(c[2]), "+f"(c[3])
      : "r"(a[0]), "r"(a[1]), "r"(a[2]), "r"(a[3]), "r"(b[0]), "r"(b[1]));
}

__device__ __forceinline__ void mma_f16(float c[4], const uint32_t a[4],
                                        const uint32_t b[2]) {
  asm volatile(
      "mma.sync.aligned.m16n8k16.row.col.f32.f16.f16.f32 "
      "{%0,%1,%2,%3}, {%4,%5,%6,%7}, {%8,%9}, {%0,%1,%2,%3};\n"
      : "+f"(c[0]), "+f"(c[1]), "+f"(c[2]), "+f"(c[3])
      : "r"(a[0]), "r"(a[1]), "r"(a[2]), "r"(a[3]), "r"(b[0]), "r"(b[1]));
}

__device__ __forceinline__ void ldsm4(uint32_t r[4], uint32_t saddr) {
  asm volatile(
      "ldmatrix.sync.aligned.m8n8.x4.shared.b16 {%0,%1,%2,%3}, [%4];"
      : "=r"(r[0]), "=r"(r[1]), "=r"(r[2]), "=r"(r[3])
      : "r"(saddr));
}

__device__ __forceinline__ void cp_async16(uint32_t dst, const void* src,
                                           bool pred) {
  int sz = pred ? 16 : 0;
  asm volatile("cp.async.cg.shared.global [%0], [%1], 16, %2;\n" ::"r"(dst),
               "l"(src), "r"(sz));
}
__device__ __forceinline__ void cp_commit() {
  asm volatile("cp.async.commit_group;\n");
}
template <int N>
__device__ __forceinline__ void cp_wait() {
  asm volatile("cp.async.wait_group %0;\n" ::"n"(N));
}

// ---------------------------------------------------------------------------
// Weight packing kernels (fp32 -> k-pair packed fp16 words)
// ---------------------------------------------------------------------------
// NN: in [batch][Ktot][N] -> out [batch][Ktot/2][N]
__global__ void pack_nn(const float* __restrict__ in, uint32_t* __restrict__ out,
                        int N, int Ktot) {
  size_t zi = (size_t)blockIdx.z * Ktot * N;
  size_t zo = (size_t)blockIdx.z * (Ktot / 2) * N;
  int n = blockIdx.x * 256 + threadIdx.x;
  int kp = blockIdx.y;
  float a = in[zi + (size_t)(2 * kp) * N + n];
  float b = in[zi + (size_t)(2 * kp + 1) * N + n];
  out[zo + (size_t)kp * N + n] = h2u(__floats2half2_rn(a, b));
}

// TR: in [N][K] -> out [K/2][N]  (B^T pack). Tile 32 n x 64 k.
__global__ void pack_tr(const float* __restrict__ in, uint32_t* __restrict__ out,
                        int N, int K) {
  __shared__ float s[32][65];
  int n0 = blockIdx.x * 32, k0 = blockIdx.y * 64;
  int tid = threadIdx.x;
#pragma unroll
  for (int l = 0; l < 8; l++) {
    int idx = tid + l * 256;
    int r = idx >> 6, c = idx & 63;
    s[r][c] = in[(size_t)(n0 + r) * K + k0 + c];
  }
  __syncthreads();
#pragma unroll
  for (int l = 0; l < 4; l++) {
    int idx = tid + l * 256;
    int i = idx >> 5, j = idx & 31;  // i: kp-local (0..31), j: n-local
    out[(size_t)(k0 / 2 + i) * N + n0 + j] =
        h2u(__floats2half2_rn(s[j][2 * i], s[j][2 * i + 1]));
  }
}

// ---------------------------------------------------------------------------
// RMSNorm (optional fp16 second output)
// ---------------------------------------------------------------------------
__global__ void rmsnorm_kernel(const float* __restrict__ in,
                               const float* __restrict__ w,
                               float* __restrict__ out,
                               __half* __restrict__ out16, int dim) {
  int t = blockIdx.x;
  const float* r = in + (size_t)t * dim;
  float s = 0.f;
  for (int i = threadIdx.x; i < dim; i += 256) {
    float v = r[i];
    s += v * v;
  }
  for (int o = 16; o; o >>= 1) s += __shfl_xor_sync(~0u, s, o);
  __shared__ float red[8];
  if ((threadIdx.x & 31) == 0) red[threadIdx.x >> 5] = s;
  __syncthreads();
  if (threadIdx.x == 0) {
    float tt = 0.f;
    for (int i = 0; i < 8; i++) tt += red[i];
    red[0] = tt;
  }
  __syncthreads();
  float inv = rsqrtf(red[0] / (float)dim + EPS);
  for (int i = threadIdx.x * 2; i < dim; i += 512) {
    float v0 = r[i] * inv * w[i];
    float v1 = r[i + 1] * inv * w[i + 1];
    out[(size_t)t * dim + i] = v0;
    out[(size_t)t * dim + i + 1] = v1;
    if (out16) {
      __half2 h = __floats2half2_rn(v0, v1);
      *(__half2*)&out16[(size_t)t * dim + i] = h;
    }
  }
}

// ---------------------------------------------------------------------------
// Per-head Q/K RMSNorm + RoPE
// ---------------------------------------------------------------------------
__global__ void qknorm_rope_kernel(const float* __restrict__ qkv,
                                   const int* __restrict__ positions,
                                   const float* __restrict__ qn,
                                   const float* __restrict__ kn,
                                   float* __restrict__ qout,
                                   float* __restrict__ kout) {
  int t = blockIdx.x, hh = blockIdx.y, d = threadIdx.x;
  const float* src;
  const float* w;
  float* dst;
  if (hh < NH) {
    src = qkv + (size_t)t * QKVW + hh * D;
    w = qn;
    dst = qout + ((size_t)t * NH + hh) * D;
  } else {
    int kv = hh - NH;
    src = qkv + (size_t)t * QKVW + NH * D + kv * D;
    w = kn;
    dst = kout + ((size_t)t * NKV + kv) * D;
  }
  float v = src[d];
  float s = v * v;
  for (int o = 16; o; o >>= 1) s += __shfl_xor_sync(~0u, s, o);
  __shared__ float red[4];
  if ((d & 31) == 0) red[d >> 5] = s;
  __syncthreads();
  float tot = red[0] + red[1] + red[2] + red[3];
  float nv = v * rsqrtf(tot / (float)D + EPS) * w[d];
  __shared__ float sh[128];
  sh[d] = nv;
  __syncthreads();
  int sidx = t & (S - 1);
  float pos = (float)positions[sidx];
  float res;
  if (d < ROT / 2) {
    float ang = pos * powf(THETA, -(float)d / (float)(ROT / 2));
    res = sh[d] * cosf(ang) - sh[d + ROT / 2] * sinf(ang);
  } else if (d < ROT) {
    int i2 = d - ROT / 2;
    float ang = pos * powf(THETA, -(float)i2 / (float)(ROT / 2));
    res = sh[d] * cosf(ang) + sh[d - ROT / 2] * sinf(ang);
  } else {
    res = nv;
  }
  dst[d] = res;
}

// ---------------------------------------------------------------------------
// tf32 GEMM (attention: scores + AV)
// ---------------------------------------------------------------------------
enum GemmMode { M_SCORES = 0, M_AV, M_GATE };

struct GemmP {
  int mode;
  const float* A;
  const float* Bm;
  float* C;
  __half* C16;
  int M, N, K, lda, ldb, ldc;
  int transB;
};

constexpr int APAD = 20;
constexpr int BPAD = 136;
constexpr int STAGES = 4;
constexpr int STW = 128 * APAD;
constexpr int GEMM_DSMEM = STAGES * 2 * STW * 4;

extern __shared__ uint32_t dynsmem[];

__global__ __launch_bounds__(256, 2) void gemm_tc(GemmP p) {
  int z = blockIdx.z;
  const float* Ab = p.A;
  const float* Bb = p.Bm;
  float* Cb = p.C;
  __half* Cb16 = p.C16;
  int Meff = p.M;

  if (p.mode == M_SCORES) {
    int b = z >> 3, h = z & 7;
    Ab = p.A + ((size_t)(b * S) * NH + h) * D;
    Bb = p.Bm + ((size_t)(b * S) * NKV + (h >> 2)) * D;
    Cb = p.C + (size_t)z * S * S;
  } else if (p.mode == M_AV) {
    int b = z >> 3, h = z & 7;
    Ab = p.A + (size_t)z * S * S;
    Bb = p.Bm + (size_t)(b * S) * QKVW + (size_t)(NH + NKV) * D + (h >> 2) * D;
    Cb = p.C + (size_t)(b * S) * (NH * D) + h * D;
    Cb16 = p.C16 + (size_t)(b * S) * (NH * D) + h * D;
  }

  int m0 = blockIdx.y * 128, n0 = blockIdx.x * 128;
  if (m0 >= Meff) return;
  if (p.mode == M_SCORES && n0 > m0 + 127) return;

  int kend = p.K;
  if (p.mode == M_AV) kend = min(p.K, m0 + 128);
  int nk = kend >> 4;

  uint32_t* Asm = dynsmem;
  uint32_t* Bsm = dynsmem + STAGES * STW;

  int tid = threadIdx.x;
  int lane = tid & 31, wid = tid >> 5;
  int warp_m = wid & 1, warp_n = wid >> 1;
  int gid = lane >> 2, tig = lane & 3;

  uint32_t as_base = (uint32_t)__cvta_generic_to_shared(Asm);
  uint32_t bs_base = (uint32_t)__cvta_generic_to_shared(Bsm);
  int lm_row = (lane & 15);
  int lm_col = (lane >> 4) << 2;

  float acc[4][4][4];
#pragma unroll
  for (int a = 0; a < 4; a++)
#pragma unroll
    for (int b = 0; b < 4; b++)
#pragma unroll
      for (int c = 0; c < 4; c++) acc[a][b][c] = 0.f;

  int a_row0 = tid >> 2, a_kq = (tid & 3) * 4;
  const float* a_src0;
  const float* a_src1;
  {
    int gm0 = m0 + a_row0, gm1 = m0 + a_row0 + 64;
    a_src0 = (gm0 < Meff) ? Ab + (size_t)gm0 * p.lda : Ab;
    a_src1 = (gm1 < Meff) ? Ab + (size_t)gm1 * p.lda : Ab;
  }
  bool a_v0 = (m0 + a_row0) < Meff;
  bool a_v1 = (m0 + a_row0 + 64) < Meff;

  auto issue = [&](int it, int st) {
    if (it < nk) {
      int k0 = it << 4;
      cp_async16(as_base + (uint32_t)(st * STW + a_row0 * APAD + a_kq) * 4u,
                 a_src0 + k0 + a_kq, a_v0);
      cp_async16(
          as_base + (uint32_t)(st * STW + (a_row0 + 64) * APAD + a_kq) * 4u,
          a_src1 + k0 + a_kq, a_v1);
      if (p.transB) {
        int n = tid >> 2, kq = (tid & 3) * 4;
        cp_async16(bs_base + (uint32_t)(st * STW + n * APAD + kq) * 4u,
                   Bb + (size_t)(n0 + n) * p.ldb + k0 + kq, true);
        cp_async16(bs_base + (uint32_t)(st * STW + (n + 64) * APAD + kq) * 4u,
                   Bb + (size_t)(n0 + n + 64) * p.ldb + k0 + kq, true);
      } else {
        int kk = tid >> 5, nq = (tid & 31) * 4;
        cp_async16(bs_base + (uint32_t)(st * STW + kk * BPAD + nq) * 4u,
                   Bb + (size_t)(k0 + kk) * p.ldb + n0 + nq, true);
        cp_async16(bs_base + (uint32_t)(st * STW + (kk + 8) * BPAD + nq) * 4u,
                   Bb + (size_t)(k0 + kk + 8) * p.ldb + n0 + nq, true);
      }
    }
    cp_commit();
  };

  issue(0, 0);
  issue(1, 1);
  issue(2, 2);

  int cur = 0;
  for (int it = 0; it < nk; it++) {
    cp_wait<STAGES - 2>();
    __syncthreads();
    issue(it + 3, (cur + 3) & (STAGES - 1));

    const uint32_t* Bsp = Bsm + cur * STW;
#pragma unroll
    for (int ks = 0; ks < 16; ks += 8) {
      uint32_t afr[4][4];
#pragma unroll
      for (int mt = 0; mt < 4; mt++) {
        int row = warp_m * 64 + mt * 16 + lm_row;
        uint32_t saddr =
            as_base + (uint32_t)(cur * STW + row * APAD + ks + lm_col) * 4u;
        ldsm4(afr[mt], saddr);
      }
      uint32_t bfr[4][2];
      if (p.transB) {
#pragma unroll
        for (int nt = 0; nt < 4; nt++) {
          int ncol = warp_n * 32 + nt * 8 + gid;
          bfr[nt][0] = Bsp[ncol * APAD + ks + tig];
          bfr[nt][1] = Bsp[ncol * APAD + ks + tig + 4];
        }
      } else {
#pragma unroll
        for (int nt = 0; nt < 4; nt++) {
          int ncol = warp_n * 32 + nt * 8 + gid;
          bfr[nt][0] = Bsp[(ks + tig) * BPAD + ncol];
          bfr[nt][1] = Bsp[(ks + tig + 4) * BPAD + ncol];
        }
      }
#pragma unroll
      for (int mt = 0; mt < 4; mt++)
#pragma unroll
        for (int nt = 0; nt < 4; nt++) mma_tf32(acc[mt][nt], afr[mt], bfr[nt]);
    }
    cur = (cur + 1) & (STAGES - 1);
  }

#pragma unroll
  for (int mt = 0; mt < 4; mt++) {
#pragma unroll
    for (int nt = 0; nt < 4; nt++) {
#pragma unroll
      for (int ee = 0; ee < 4; ee++) {
        int gm = m0 + warp_m * 64 + mt * 16 + gid + (ee >= 2 ? 8 : 0);
        int gn = n0 + warp_n * 32 + nt * 8 + tig * 2 + (ee & 1);
        if (gm >= Meff) continue;
        float v = acc[mt][nt][ee];
        if (p.mode == M_SCORES) {
          if (gn > gm) continue;
          v *= SCALE;
        }
        Cb[(size_t)gm * p.ldc + gn] = v;
        if (p.mode == M_AV) Cb16[(size_t)gm * p.ldc + gn] = __float2half(v);
      }
    }
  }
}

// ---------------------------------------------------------------------------
// Unified fp16 GEMM over PACKED weights, 4-stage cp.async pipeline.
// A: fp16 [m][lda] (optional gather). B: packed u32 words [K/2][ldbw].
// Modes: FM_GU (fused SiLU -> fp16; interleaved gate/up cols),
//        FM_DN (scatter-atomic), FM_QKV (+bias), FM_WO (+resid), FM_SDN.
// ---------------------------------------------------------------------------
enum F16Mode { FM_GU = 0, FM_DN, FM_QKV, FM_WO, FM_SDN };

struct F16P {
  int mode;
  const __half* A;
  const uint32_t* Bw;
  __half* Ch;
  float* Cf;
  const float* bias;
  const float* resid;
  const int* gidx;
  const int* cnt;
  const float* wslot;
  int lda, ldbw, ldc, K, M;
  long long a_zs, b_zs, c_zs;  // b_zs in words
};

constexpr int HAPAD = 40;               // halves per A row
constexpr int F16_ASTW = 128 * HAPAD;   // halves per A stage (5120)
constexpr int F16_BW = 16 * 136;        // words per B stage (2176)
constexpr int F16_STAGES = 4;
constexpr int F16_DSMEM =
    F16_STAGES * (F16_ASTW * 2 + F16_BW * 4);  // 40960 + 34816 = 75776 B

__global__ __launch_bounds__(256, 2) void gemm_f16(F16P p) {
  int z = blockIdx.z;
  int Meff = p.cnt ? min(p.cnt[z], CAP) : p.M;
  int m0 = blockIdx.y * 128;
  if (m0 >= Meff) return;

  const __half* Ab = p.A + (size_t)z * p.a_zs;
  const uint32_t* Bw = p.Bw + (size_t)z * p.b_zs;
  const int* gidx = (p.mode == FM_GU && p.gidx) ? p.gidx + z * CAP : nullptr;
  const int* tokz = (p.mode == FM_DN) ? p.gidx + z * CAP : nullptr;
  const float* wz = (p.mode == FM_DN) ? p.wslot + z * CAP : nullptr;
  int n0 = blockIdx.x * 128;
  int n0g = blockIdx.x * 64;

  uint32_t* BsAll = dynsmem + (F16_STAGES * F16_ASTW / 2);

  int tid = threadIdx.x;
  int lane = tid & 31, wid = tid >> 5;
  int warp_m = wid & 1, warp_n = wid >> 1;
  int gid = lane >> 2, tig = lane & 3;

  uint32_t as_base = (uint32_t)__cvta_generic_to_shared(dynsmem);
  uint32_t bs_base = (uint32_t)__cvta_generic_to_shared(BsAll);

  int nk = p.K >> 5;  // K-tile 32 -> 16 kp rows/stage

  float acc[4][4][4];
#pragma unroll
  for (int a = 0; a < 4; a++)
#pragma unroll
    for (int b = 0; b < 4; b++)
#pragma unroll
      for (int c = 0; c < 4; c++) acc[a][b][c] = 0.f;

  int a_row0 = tid >> 2, a_kq = (tid & 3) * 8;
  const __half* a_src0;
  const __half* a_src1;
  {
    int gm0 = m0 + a_row0, gm1 = m0 + a_row0 + 64;
    a_src0 = (gm0 < Meff)
                 ? (gidx ? Ab + (size_t)gidx[gm0] * p.lda
                         : Ab + (size_t)gm0 * p.lda)
                 : Ab;
    a_src1 = (gm1 < Meff)
                 ? (gidx ? Ab + (size_t)gidx[gm1] * p.lda
                         : Ab + (size_t)gm1 * p.lda)
                 : Ab;
  }
  bool a_v0 = (m0 + a_row0) < Meff;
  bool a_v1 = (m0 + a_row0 + 64) < Meff;

  // B chunk mapping (cp.async straight from packed weights)
  int b_kp0 = tid >> 5, b_nq0 = (tid & 31) * 4;
  int b_kp1 = (tid + 256) >> 5, b_nq1 = ((tid + 256) & 31) * 4;
  auto bcol = [&](int n) -> int {
    if (p.mode == FM_GU) {
      int grp = n >> 4;
      int isup = (n >> 3) & 1;
      int cc = grp * 8 + (n & 7);
      return (isup ? FI : 0) + n0g + cc;  // FI == FSH
    }
    return n0 + n;
  };
  int b_c0 = bcol(b_nq0);
  int b_c1 = bcol(b_nq1);

  auto issue = [&](int it, int st) {
    if (it < nk) {
      int k0h = it << 5;
      cp_async16(
          as_base + (uint32_t)(st * F16_ASTW + a_row0 * HAPAD + a_kq) * 2u,
          a_src0 + k0h + a_kq, a_v0);
      cp_async16(
          as_base +
              (uint32_t)(st * F16_ASTW + (a_row0 + 64) * HAPAD + a_kq) * 2u,
          a_src1 + k0h + a_kq, a_v1);
      int kp0 = it << 4;
      cp_async16(bs_base + (uint32_t)(st * F16_BW + b_kp0 * 136 + b_nq0) * 4u,
                 Bw + (size_t)(kp0 + b_kp0) * p.ldbw + b_c0, true);
      cp_async16(bs_base + (uint32_t)(st * F16_BW + b_kp1 * 136 + b_nq1) * 4u,
                 Bw + (size_t)(kp0 + b_kp1) * p.ldbw + b_c1, true);
    }
    cp_commit();
  };

  issue(0, 0);
  issue(1, 1);
  issue(2, 2);

  int cur = 0;
  for (int it = 0; it < nk; it++) {
    cp_wait<F16_STAGES - 2>();
    __syncthreads();
    issue(it + 3, (cur + 3) & (F16_STAGES - 1));

    const uint32_t* Bsp = BsAll + cur * F16_BW;
#pragma unroll
    for (int ks = 0; ks < 2; ks++) {
      uint32_t afr[4][4];
#pragma unroll
      for (int mt = 0; mt < 4; mt++) {
        int row = warp_m * 64 + mt * 16 + (lane & 15);
        uint32_t saddr =
            as_base + (uint32_t)(cur * F16_ASTW + row * HAPAD + ks * 16 +
                                 ((lane >> 4) << 3)) *
                          2u;
        ldsm4(afr[mt], saddr);
      }
      uint32_t bfr[4][2];
      int kpb = ks * 8;
#pragma unroll
      for (int nt = 0; nt < 4; nt++) {
        int ncol = warp_n * 32 + nt * 8 + gid;
        bfr[nt][0] = Bsp[(kpb + tig) * 136 + ncol];
        bfr[nt][1] = Bsp[(kpb + 4 + tig) * 136 + ncol];
      }
#pragma unroll
      for (int mt = 0; mt < 4; mt++)
#pragma unroll
        for (int nt = 0; nt < 4; nt++) mma_f16(acc[mt][nt], afr[mt], bfr[nt]);
    }
    cur = (cur + 1) & (F16_STAGES - 1);
  }

  if (p.mode == FM_GU) {
    __half* Chb = p.Ch + (size_t)z * p.c_zs;
#pragma unroll
    for (int mt = 0; mt < 4; mt++) {
#pragma unroll
      for (int q = 0; q < 2; q++) {
#pragma unroll
        for (int half_e = 0; half_e < 2; half_e++) {
          int gm = m0 + warp_m * 64 + mt * 16 + gid + half_e * 8;
          if (gm >= Meff) continue;
          float g0 = acc[mt][2 * q][half_e * 2 + 0];
          float g1 = acc[mt][2 * q][half_e * 2 + 1];
          float u0 = acc[mt][2 * q + 1][half_e * 2 + 0];
          float u1 = acc[mt][2 * q + 1][half_e * 2 + 1];
          float a0 = (g0 / (1.f + expf(-g0))) * u0;
          float a1 = (g1 / (1.f + expf(-g1))) * u1;
          int cc = n0g + (2 * warp_n + q) * 8 + tig * 2;
          __half2 h = __floats2half2_rn(a0, a1);
          *(__half2*)&Chb[(size_t)gm * p.ldc + cc] = h;
        }
      }
    }
  } else if (p.mode == FM_DN) {
#pragma unroll
    for (int mt = 0; mt < 4; mt++) {
#pragma unroll
      for (int nt = 0; nt < 4; nt++) {
#pragma unroll
        for (int ee = 0; ee < 4; ee++) {
          int gm = m0 + warp_m * 64 + mt * 16 + gid + (ee >= 2 ? 8 : 0);
          if (gm >= Meff) continue;
          int gn = n0 + warp_n * 32 + nt * 8 + tig * 2 + (ee & 1);
          int t = tokz[gm];
          float w = wz[gm];
          atomicAdd(&p.Cf[(size_t)t * p.ldc + gn], acc[mt][nt][ee] * w);
        }
      }
    }
  } else {
#pragma unroll
    for (int mt = 0; mt < 4; mt++) {
#pragma unroll
      for (int nt = 0; nt < 4; nt++) {
#pragma unroll
        for (int ee = 0; ee < 4; ee++) {
          int gm = m0 + warp_m * 64 + mt * 16 + gid + (ee >= 2 ? 8 : 0);
          if (gm >= Meff) continue;
          int gn = n0 + warp_n * 32 + nt * 8 + tig * 2 + (ee & 1);
          float v = acc[mt][nt][ee];
          if (p.mode == FM_QKV)
            v += p.bias[gn];
          else if (p.mode == FM_WO)
            v += p.resid[(size_t)gm * p.ldc + gn];
          p.Cf[(size_t)gm * p.ldc + gn] = v;
        }
      }
    }
  }
}

// ---------------------------------------------------------------------------
// fp32 SIMT GEMM (tiny gate GEMM -> exact routing inputs)
// ---------------------------------------------------------------------------
__global__ __launch_bounds__(256) void gemm_kernel(GemmP p) {
  const float* Ab = p.A;
  const float* Bb = p.Bm;
  float* Cb = p.C;
  int Meff = p.M;

  int m0 = blockIdx.y * 64, n0 = blockIdx.x * 64;
  if (m0 >= Meff) return;

  __shared__ float As[16][68];
  __shared__ float Bs[16][68];
  int tid = threadIdx.x, tx = tid & 15, ty = tid >> 4;
  float acc[4][4] = {};

  for (int k0 = 0; k0 < p.K; k0 += 16) {
#pragma unroll
    for (int l = 0; l < 4; l++) {
      int i = tid + l * 256;
      int row = i >> 4, col = i & 15;
      int gm = m0 + row;
      float v = 0.f;
      if (gm < Meff) v = Ab[(size_t)gm * p.lda + k0 + col];
      As[col][row] = v;
    }
#pragma unroll
    for (int l = 0; l < 4; l++) {
      int i = tid + l * 256;
      if (p.transB) {
        int col = i >> 4, kk = i & 15;
        Bs[kk][col] = Bb[(size_t)(n0 + col) * p.ldb + (k0 + kk)];
      } else {
        int kk = i >> 6, col = i & 63;
        Bs[kk][col] = Bb[(size_t)(k0 + kk) * p.ldb + (n0 + col)];
      }
    }
    __syncthreads();
#pragma unroll
    for (int kk = 0; kk < 16; kk++) {
      float4 a4 = *(const float4*)(&As[kk][ty * 4]);
      float4 b4 = *(const float4*)(&Bs[kk][tx * 4]);
      float av[4] = {a4.x, a4.y, a4.z, a4.w};
      float bv[4] = {b4.x, b4.y, b4.z, b4.w};
#pragma unroll
      for (int i = 0; i < 4; i++)
#pragma unroll
        for (int j = 0; j < 4; j++) acc[i][j] += av[i] * bv[j];
    }
    __syncthreads();
  }

#pragma unroll
  for (int i = 0; i < 4; i++) {
    int gm = m0 + ty * 4 + i;
    if (gm >= Meff) continue;
#pragma unroll
    for (int j = 0; j < 4; j++) {
      int gn = n0 + tx * 4 + j;
      Cb[(size_t)gm * p.ldc + gn] = acc[i][j];
    }
  }
}

// ---------------------------------------------------------------------------
// Row softmax, causal-aware.
// ---------------------------------------------------------------------------
__global__ void softmax_kernel(float* __restrict__ sc) {
  size_t row = blockIdx.x;
  int q = (int)(row & (S - 1));
  int len = q + 1;
  int fill_end = ((q >> 7) + 1) << 7;
  float* p = sc + row * (size_t)S;
  __shared__ float red[8];
  float mx = -INFINITY;
  for (int i = threadIdx.x; i < len; i += 256) mx = fmaxf(mx, p[i]);
  for (int o = 16; o; o >>= 1) mx = fmaxf(mx, __shfl_xor_sync(~0u, mx, o));
  if ((threadIdx.x & 31) == 0) red[threadIdx.x >> 5] = mx;
  __syncthreads();
  if (threadIdx.x == 0) {
    float m = red[0];
    for (int i = 1; i < 8; i++) m = fmaxf(m, red[i]);
    red[0] = m;
  }
  __syncthreads();
  mx = red[0];
  __syncthreads();
  float sum = 0.f;
  for (int i = threadIdx.x; i < len; i += 256) {
    float e = expf(p[i] - mx);
    p[i] = e;
    sum += e;
  }
  for (int o = 16; o; o >>= 1) sum += __shfl_xor_sync(~0u, sum, o);
  if ((threadIdx.x & 31) == 0) red[threadIdx.x >> 5] = sum;
  __syncthreads();
  if (threadIdx.x == 0) {
    float t = 0.f;
    for (int i = 0; i < 8; i++) t += red[i];
    red[0] = t;
  }
  __syncthreads();
  float inv = 1.f / red[0];
  for (int i = threadIdx.x; i < len; i += 256) p[i] *= inv;
  for (int i = len + threadIdx.x; i < fill_end; i += 256) p[i] = 0.f;
}

// ---------------------------------------------------------------------------
// Routing
// ---------------------------------------------------------------------------
__global__ void route_kernel(const float* __restrict__ logits,
                             const float* __restrict__ gate_b,
                             int* __restrict__ topi, float* __restrict__ fw) {
  int t = blockIdx.x * blockDim.x + threadIdx.x;
  if (t >= T) return;
  float corr[E];
  const float* lg = logits + (size_t)t * E;
  for (int e = 0; e < E; e++) {
    float s = 1.f / (1.f + expf(-lg[e]));
    corr[e] = s + gate_b[e];
  }
  float grp[NG];
  for (int g = 0; g < NG; g++) {
    float m1 = -INFINITY, m2 = -INFINITY;
    for (int i = 0; i < E / NG; i++) {
      float v = corr[g * (E / NG) + i];
      if (v > m1) {
        m2 = m1;
        m1 = v;
      } else if (v > m2) {
        m2 = v;
      }
    }
    grp[g] = m1 + m2;
  }
  unsigned gsel = 0;
  for (int it = 0; it < TG; it++) {
    float best = -INFINITY;
    int bi = 0;
    for (int g = 0; g < NG; g++)
      if (!((gsel >> g) & 1u) && grp[g] > best) {
        best = grp[g];
        bi = g;
      }
    gsel |= 1u << bi;
  }
  unsigned long long esel = 0ull;
  int sel[TK];
  float ws[TK];
  float wsum = 0.f;
  for (int it = 0; it < TK; it++) {
    float best = -INFINITY;
    int bi = 0;
    for (int e = 0; e < E; e++) {
      if (!((gsel >> (e >> 3)) & 1u)) continue;
      if ((esel >> e) & 1ull) continue;
      if (corr[e] > best) {
        best = corr[e];
        bi = e;
      }
    }
    esel |= 1ull << bi;
    sel[it] = bi;
    float s = corr[bi] - gate_b[bi];
    ws[it] = s;
    wsum += s;
  }
  float inv = 1.f / wsum;
  for (int j = 0; j < TK; j++) {
    topi[t * TK + j] = sel[j];
    fw[t * TK + j] = ws[j] * inv;
  }
}

__global__ void zero_cnt_kernel(int* __restrict__ cnt) {
  if (threadIdx.x < E) cnt[threadIdx.x] = 0;
}

__global__ void assign_kernel(const int* __restrict__ topi,
                              const float* __restrict__ fw,
                              int* __restrict__ cnt, int* __restrict__ tok,
                              float* __restrict__ wslot) {
  int i = blockIdx.x * blockDim.x + threadIdx.x;
  if (i >= T * TK) return;
  int e = topi[i];
  int p = atomicAdd(&cnt[e], 1);
  if (p < CAP) {
    tok[e * CAP + p] = i / TK;
    wslot[e * CAP + p] = fw[i];
  }
}

// ---------------------------------------------------------------------------
// Final: out = h2 + comb
// ---------------------------------------------------------------------------
__global__ void final_kernel(const float* __restrict__ h2,
                             const float* __restrict__ comb,
                             float* __restrict__ out) {
  size_t i = (size_t)blockIdx.x * 256 + threadIdx.x;
  if (i < (size_t)T * H) out[i] = h2[i] + comb[i];
}

// ---------------------------------------------------------------------------
// Host launcher
// ---------------------------------------------------------------------------
extern "C" void kernel_launch(void* const* d_in, const int* in_sizes, int n_in,
                              void* d_out, int out_size) {
  const float* x = (const float*)d_in[0];
  const int* positions = (const int*)d_in[1];
  const float* ln1_w = (const float*)d_in[2];
  const float* ln2_w = (const float*)d_in[3];
  const float* wqkv = (const float*)d_in[4];
  const float* bqkv = (const float*)d_in[5];
  const float* qn_w = (const float*)d_in[6];
  const float* kn_w = (const float*)d_in[7];
  const float* wo = (const float*)d_in[8];
  const float* gate_w = (const float*)d_in[9];
  const float* gate_b = (const float*)d_in[10];
  const float* w_gu = (const float*)d_in[11];
  const float* w_dn = (const float*)d_in[12];
  const float* sw_gu = (const float*)d_in[13];
  const float* sw_dn = (const float*)d_in[14];
  float* out = (float*)d_out;

  static bool attr_set = false;
  if (!attr_set) {
    cudaFuncSetAttribute(gemm_tc, cudaFuncAttributeMaxDynamicSharedMemorySize,
                         GEMM_DSMEM);
    cudaFuncSetAttribute(gemm_f16, cudaFuncAttributeMaxDynamicSharedMemorySize,
                         F16_DSMEM);
    attr_set = true;
  }

  float* scr = nullptr;
  cudaGetSymbolAddress((void**)&scr, g_scratch);
  int* topi = nullptr;
  cudaGetSymbolAddress((void**)&topi, g_topi);
  int* cnt = nullptr;
  cudaGetSymbolAddress((void**)&cnt, g_cnt);
  int* tok = nullptr;
  cudaGetSymbolAddress((void**)&tok, g_tok);
  float* wslot = nullptr;
  cudaGetSymbolAddress((void**)&wslot, g_wslot);
  __half* xt16 = nullptr;
  cudaGetSymbolAddress((void**)&xt16, g_xt16);
  __half* bh16 = nullptr;
  cudaGetSymbolAddress((void**)&bh16, g_bh16);
  __half* aout16 = nullptr;
  cudaGetSymbolAddress((void**)&aout16, g_aout16);
  __half* shact16 = nullptr;
  cudaGetSymbolAddress((void**)&shact16, g_shact16);
  __half* act16 = nullptr;
  cudaGetSymbolAddress((void**)&act16, g_act16);
  uint32_t* wgu16 = nullptr;
  cudaGetSymbolAddress((void**)&wgu16, g_wgu16);
  uint32_t* wdn16 = nullptr;
  cudaGetSymbolAddress((void**)&wdn16, g_wdn16);
  uint32_t* wqkv16 = nullptr;
  cudaGetSymbolAddress((void**)&wqkv16, g_wqkv16);
  uint32_t* wo16 = nullptr;
  cudaGetSymbolAddress((void**)&wo16, g_wo16);
  uint32_t* sgu16 = nullptr;
  cudaGetSymbolAddress((void**)&sgu16, g_sgu16);
  uint32_t* sdn16 = nullptr;
  cudaGetSymbolAddress((void**)&sdn16, g_sdn16);

  float* bh = scr + OFF_H;
  float* bqkvb = scr + OFF_QKV;
  float* bq = scr + OFF_Q;
  float* bk = scr + OFF_K;
  float* bsc = scr + OFF_SC;
  float* baout = scr + OFF_AOUT;
  float* bh2 = scr + OFF_H2;
  float* bxt = scr + OFF_XT;
  float* blog = scr + OFF_LOG;
  float* bfw = scr + OFF_FW;
  float* bcomb = scr + OFF_COMB;

  // 0. pack weights -> fp16 k-pair layout
  pack_nn<<<dim3((2 * FI) / 256, H / 2, E), 256>>>(w_gu, wgu16, 2 * FI, H);
  pack_nn<<<dim3(H / 256, FI / 2, E), 256>>>(w_dn, wdn16, H, FI);
  pack_nn<<<dim3((2 * FSH) / 256, H / 2, 1), 256>>>(sw_gu, sgu16, 2 * FSH, H);
  pack_nn<<<dim3(H / 256, FSH / 2, 1), 256>>>(sw_dn, sdn16, H, FSH);
  pack_tr<<<dim3(QKVW / 32, H / 64), 256>>>(wqkv, wqkv16, QKVW, H);
  pack_tr<<<dim3(H / 32, (NH * D) / 64), 256>>>(wo, wo16, H, NH * D);

  // 1. rmsnorm1 (fp32 + fp16)
  rmsnorm_kernel<<<T, 256>>>(x, ln1_w, bh, bh16, H);

  // 2. qkv (fp16, packed transposed weights)
  {
    F16P p{};
    p.mode = FM_QKV;
    p.A = bh16; p.Bw = wqkv16; p.Cf = bqkvb; p.bias = bqkv;
    p.lda = H; p.ldbw = QKVW; p.ldc = QKVW; p.K = H; p.M = T;
    gemm_f16<<<dim3(QKVW / 128, T / 128, 1), 256, F16_DSMEM>>>(p);
  }

  // 3. q/k rmsnorm + rope
  qknorm_rope_kernel<<<dim3(T, NH + NKV), 128>>>(bqkvb, positions, qn_w, kn_w,
                                                 bq, bk);

  // 4. scores (tf32)
  {
    GemmP p{};
    p.mode = M_SCORES;
    p.A = bq; p.Bm = bk; p.C = bsc;
    p.M = S; p.N = S; p.K = D;
    p.lda = NH * D; p.ldb = NKV * D; p.ldc = S; p.transB = 1;
    gemm_tc<<<dim3(S / 128, S / 128, B * NH), 256, GEMM_DSMEM>>>(p);
  }

  // 5. softmax
  softmax_kernel<<<B * NH * S, 256>>>(bsc);

  // 6. attn @ v (tf32; dual fp32+fp16 out)
  {
    GemmP p{};
    p.mode = M_AV;
    p.A = bsc; p.Bm = bqkvb; p.C = baout; p.C16 = aout16;
    p.M = S; p.N = D; p.K = S;
    p.lda = S; p.ldb = QKVW; p.ldc = NH * D; p.transB = 0;
    gemm_tc<<<dim3(D / 128, S / 128, B * NH), 256, GEMM_DSMEM>>>(p);
  }

  // 7. h2 = x + aout @ wo^T  (fp16 packed)
  {
    F16P p{};
    p.mode = FM_WO;
    p.A = aout16; p.Bw = wo16; p.Cf = bh2; p.resid = x;
    p.lda = NH * D; p.ldbw = H; p.ldc = H; p.K = NH * D; p.M = T;
    gemm_f16<<<dim3(H / 128, T / 128, 1), 256, F16_DSMEM>>>(p);
  }

  // 8. rmsnorm2 (fp32 + fp16)
  rmsnorm_kernel<<<T, 256>>>(bh2, ln2_w, bxt, xt16, H);

  // 9. gate logits (exact fp32)
  {
    GemmP p{};
    p.mode = M_GATE;
    p.A = bxt; p.Bm = gate_w; p.C = blog;
    p.M = T; p.N = E; p.K = H;
    p.lda = H; p.ldb = H; p.ldc = E; p.transB = 1;
    gemm_kernel<<<dim3(1, T / 64, 1), 256>>>(p);
  }

  // 10. routing
  route_kernel<<<T / 256, 256>>>(blog, gate_b, topi, bfw);
  zero_cnt_kernel<<<1, 64>>>(cnt);
  assign_kernel<<<(T * TK) / 256, 256>>>(topi, bfw, cnt, tok, wslot);

  // 11. shared expert: fused up-gate+SiLU (fp16) -> shact16
  {
    F16P p{};
    p.mode = FM_GU;
    p.A = xt16; p.Bw = sgu16; p.Ch = shact16;
    p.lda = H; p.ldbw = 2 * FSH; p.ldc = FSH; p.K = H; p.M = T;
    gemm_f16<<<dim3(FSH / 64, T / 128, 1), 256, F16_DSMEM>>>(p);
  }
  // 11b. shared down -> bcomb (precedes MoE scatter)
  {
    F16P p{};
    p.mode = FM_SDN;
    p.A = shact16; p.Bw = sdn16; p.Cf = bcomb;
    p.lda = FSH; p.ldbw = H; p.ldc = H; p.K = FSH; p.M = T;
    gemm_f16<<<dim3(H / 128, T / 128, 1), 256, F16_DSMEM>>>(p);
  }

  // 12. MoE up-gate fused SiLU -> act16
  {
    F16P p{};
    p.mode = FM_GU;
    p.A = xt16; p.Bw = wgu16; p.Ch = act16;
    p.gidx = tok; p.cnt = cnt;
    p.lda = H; p.ldbw = 2 * FI; p.ldc = FI; p.K = H; p.M = CAP;
    p.a_zs = 0; p.b_zs = (long long)(H / 2) * (2 * FI);
    p.c_zs = (long long)CAP * FI;
    gemm_f16<<<dim3(FI / 64, CAP / 128, E), 256, F16_DSMEM>>>(p);
  }

  // 13. MoE down, scatter-accumulate into bcomb
  {
    F16P p{};
    p.mode = FM_DN;
    p.A = act16; p.Bw = wdn16; p.Cf = bcomb;
    p.gidx = tok; p.cnt = cnt; p.wslot = wslot;
    p.lda = FI; p.ldbw = H; p.ldc = H; p.K = FI; p.M = CAP;
    p.a_zs = (long long)CAP * FI; p.b_zs = (long long)(FI / 2) * H; p.c_zs = 0;
    gemm_f16<<<dim3(H / 128, CAP / 128, E), 256, F16_DSMEM>>>(p);
  }

  // 14. out = h2 + comb
  final_kernel<<<(int)(((size_t)T * H + 255) / 256), 256>>>(bh2, bcomb, out);
}